// round 4
// baseline (speedup 1.0000x reference)
#include <cuda_runtime.h>
#include <math.h>

#define HID 96
#define HC  576
#define NH  6

typedef unsigned long long ull;

// ---------------- f32x2 packed helpers ----------------
__device__ __forceinline__ ull fma2(ull a, ull b, ull c) {
    ull d;
    asm("fma.rn.f32x2 %0, %1, %2, %3;" : "=l"(d) : "l"(a), "l"(b), "l"(c));
    return d;
}
__device__ __forceinline__ float2 unpack2(ull v) {
    float2 r;
    asm("mov.b64 {%0, %1}, %2;" : "=f"(r.x), "=f"(r.y) : "l"(v));
    return r;
}

// ---------------- scratch ----------------
__device__ float    g_x[20000 * HID];
__device__ float    g_eemb[200000 * HID];
__device__ float    g_xl[20000 * HC];
__device__ float    g_xr[20000 * HC];
__device__ float    g_logits[200000 * NH];
__device__ unsigned g_umax[20000 * NH];
__device__ float    g_den[20000 * NH];
__device__ float    g_hmean[20000 * HID];

__device__ __forceinline__ float warpsum32(float v) {
#pragma unroll
    for (int m = 16; m; m >>= 1) v += __shfl_xor_sync(0xffffffffu, v, m);
    return v;
}
__device__ __forceinline__ float gsum16(float v) {
#pragma unroll
    for (int m = 8; m; m >>= 1) v += __shfl_xor_sync(0xffffffffu, v, m);
    return v;
}

// ---------------- encoder ----------------
__global__ void encoder_kernel(const float* __restrict__ in, int Fin,
                               const float* __restrict__ W, const float* __restrict__ b,
                               const float* __restrict__ g, const float* __restrict__ beta,
                               float* __restrict__ out, int M)
{
    int w    = (blockIdx.x * blockDim.x + threadIdx.x) >> 5;
    int lane = threadIdx.x & 31;
    if (w >= M) return;
    float xin[4];
#pragma unroll
    for (int k = 0; k < 4; k++) xin[k] = (k < Fin) ? in[(size_t)w * Fin + k] : 0.f;
    float v[3];
#pragma unroll
    for (int j = 0; j < 3; j++) {
        int c = lane + 32 * j;
        float acc = b[c];
        for (int k = 0; k < Fin; k++) acc = fmaf(xin[k], W[k * HID + c], acc);
        v[j] = acc;
    }
    float mu = warpsum32(v[0] + v[1] + v[2]) * (1.f / 96.f);
    float q = 0.f;
#pragma unroll
    for (int j = 0; j < 3; j++) { float d = v[j] - mu; q = fmaf(d, d, q); }
    float rstd = rsqrtf(warpsum32(q) * (1.f / 96.f) + 1e-5f);
#pragma unroll
    for (int j = 0; j < 3; j++) {
        int c = lane + 32 * j;
        float y = (v[j] - mu) * rstd * g[c] + beta[c];
        out[(size_t)w * HID + c] = fmaxf(y, 0.f);
    }
}

// ---------------- GEMM: C[M,576] = A[M,96] @ B[96,576] ----------------
// 256 threads, tile 128x64, 8x4 per thread (f32x2 packed rows),
// double-buffered global->smem pipeline, B stored duplicated for LDS.64 pairs.
#define BM 128
#define BN 64
#define BK 32
#define PAD_AS 132
#define AS_STEP (BK * PAD_AS)          // floats per A buffer
#define BS_STEP (BK * BN * 2)          // floats per B buffer (duplicated)
#define GEMM_SMEM ((2 * AS_STEP + 2 * BS_STEP) * 4)

template<bool FUSED>
__global__ __launch_bounds__(256) void gemm96_kernel(
    const float* __restrict__ A, const float* __restrict__ B,
    const float* __restrict__ bias, float* __restrict__ C, int M,
    const int* __restrict__ src, const int* __restrict__ dst,
    const float* __restrict__ xl, const float* __restrict__ xr,
    const float* __restrict__ attw, float* __restrict__ logits)
{
    extern __shared__ float sh[];
    float* As = sh;                    // 2 x [BK][PAD_AS] (k-major, transposed)
    float* Bs = sh + 2 * AS_STEP;      // 2 x [BK][128] duplicated pairs

    int tid = threadIdx.x;
    int m0 = blockIdx.x * BM, n0 = blockIdx.y * BN;
    int tx = tid & 15, ty = tid >> 4;

    int arow = tid >> 3;               // 0..31
    int akq  = (tid & 7) * 4;          // 0,4,..,28
    int bkr  = tid >> 4;               // 0..15
    int bnq  = (tid & 15) * 4;         // 0,4,..,60

    float4 aReg[4];
    float4 bReg[2];

    // ---- load step k0 into registers ----
#define LOAD_STEP(k0)                                                          \
    {                                                                          \
        _Pragma("unroll")                                                      \
        for (int r = 0; r < 4; r++) {                                          \
            int m = m0 + arow + r * 32;                                        \
            aReg[r] = make_float4(0.f, 0.f, 0.f, 0.f);                         \
            if (m < M) aReg[r] = *(const float4*)(A + (size_t)m * 96 + (k0) + akq); \
        }                                                                      \
        _Pragma("unroll")                                                      \
        for (int r = 0; r < 2; r++)                                            \
            bReg[r] = *(const float4*)(B + (size_t)((k0) + bkr + 16 * r) * HC + n0 + bnq); \
    }

    // ---- store registers into smem buffer ----
#define STORE_STEP(buf)                                                        \
    {                                                                          \
        float* ab = As + (buf) * AS_STEP;                                      \
        _Pragma("unroll")                                                      \
        for (int r = 0; r < 4; r++) {                                          \
            int row = arow + r * 32;                                           \
            ab[(akq + 0) * PAD_AS + row] = aReg[r].x;                          \
            ab[(akq + 1) * PAD_AS + row] = aReg[r].y;                          \
            ab[(akq + 2) * PAD_AS + row] = aReg[r].z;                          \
            ab[(akq + 3) * PAD_AS + row] = aReg[r].w;                          \
        }                                                                      \
        float* bb = Bs + (buf) * BS_STEP;                                      \
        _Pragma("unroll")                                                      \
        for (int r = 0; r < 2; r++) {                                          \
            float* p = bb + (bkr + 16 * r) * 128 + bnq * 2;                    \
            float2* q = (float2*)p;                                            \
            q[0] = make_float2(bReg[r].x, bReg[r].x);                          \
            q[1] = make_float2(bReg[r].y, bReg[r].y);                          \
            q[2] = make_float2(bReg[r].z, bReg[r].z);                          \
            q[3] = make_float2(bReg[r].w, bReg[r].w);                          \
        }                                                                      \
    }

    LOAD_STEP(0);
    STORE_STEP(0);
    __syncthreads();

    ull acc2[4][4];
#pragma unroll
    for (int p = 0; p < 4; p++)
#pragma unroll
        for (int j = 0; j < 4; j++) acc2[p][j] = 0ull;

#pragma unroll
    for (int s = 0; s < 3; s++) {
        if (s < 2) LOAD_STEP((s + 1) * BK);
        const float* ab = As + (s & 1) * AS_STEP;
        const float* bb = Bs + (s & 1) * BS_STEP;
#pragma unroll 4
        for (int k = 0; k < BK; k++) {
            ulonglong2 a01 = *(const ulonglong2*)(ab + k * PAD_AS + ty * 8);
            ulonglong2 a23 = *(const ulonglong2*)(ab + k * PAD_AS + ty * 8 + 4);
            const ull* bp = (const ull*)(bb + k * 128 + tx * 8);
            ull b0 = bp[0], b1 = bp[1], b2 = bp[2], b3 = bp[3];
            ull ap[4] = {a01.x, a01.y, a23.x, a23.y};
#pragma unroll
            for (int p = 0; p < 4; p++) {
                acc2[p][0] = fma2(ap[p], b0, acc2[p][0]);
                acc2[p][1] = fma2(ap[p], b1, acc2[p][1]);
                acc2[p][2] = fma2(ap[p], b2, acc2[p][2]);
                acc2[p][3] = fma2(ap[p], b3, acc2[p][3]);
            }
        }
        if (s < 2) {
            STORE_STEP((s + 1) & 1);
            __syncthreads();
        }
    }

    float accf[8][4];
#pragma unroll
    for (int p = 0; p < 4; p++)
#pragma unroll
        for (int j = 0; j < 4; j++) {
            float2 u = unpack2(acc2[p][j]);
            accf[2 * p][j]     = u.x;
            accf[2 * p + 1][j] = u.y;
        }

    if (!FUSED) {
        float4 bq = make_float4(0.f, 0.f, 0.f, 0.f);
        if (bias) bq = *(const float4*)(bias + n0 + tx * 4);
#pragma unroll
        for (int i = 0; i < 8; i++) {
            int m = m0 + ty * 8 + i;
            if (m < M) {
                float4 o = make_float4(accf[i][0] + bq.x, accf[i][1] + bq.y,
                                       accf[i][2] + bq.z, accf[i][3] + bq.w);
                *(float4*)(C + (size_t)m * HC + n0 + tx * 4) = o;
            }
        }
    } else {
        int cbase = n0 + tx * 4;
        int h = cbase / 96;            // 4-col group never straddles a head
        float4 awv = *(const float4*)(attw + cbase);
        const unsigned fm = 0xffffffffu;
        int hprev = __shfl_up_sync(fm, h, 1, 16);
        bool leader = (tx == 0) || (hprev != h);
#pragma unroll
        for (int i = 0; i < 8; i++) {
            int m = m0 + ty * 8 + i;
            float partial = 0.f;
            if (m < M) {
                int s = src[m], d = dst[m];
                float4 xlv = *(const float4*)(xl + (size_t)s * HC + cbase);
                float4 xrv = *(const float4*)(xr + (size_t)d * HC + cbase);
                float t0 = accf[i][0] + xlv.x + xrv.x; t0 = (t0 > 0.f) ? t0 : 0.2f * t0;
                float t1 = accf[i][1] + xlv.y + xrv.y; t1 = (t1 > 0.f) ? t1 : 0.2f * t1;
                float t2 = accf[i][2] + xlv.z + xrv.z; t2 = (t2 > 0.f) ? t2 : 0.2f * t2;
                float t3 = accf[i][3] + xlv.w + xrv.w; t3 = (t3 > 0.f) ? t3 : 0.2f * t3;
                partial = t0 * awv.x + t1 * awv.y + t2 * awv.z + t3 * awv.w;
            }
#pragma unroll
            for (int off = 1; off < 16; off <<= 1) {
                float ov = __shfl_down_sync(fm, partial, off, 16);
                int   oh = __shfl_down_sync(fm, h, off, 16);
                if (tx + off < 16 && oh == h) partial += ov;
            }
            if (leader && m < M)
                atomicAdd(&logits[(size_t)m * NH + h], partial);
        }
    }
}

// ---------------- segment max ----------------
__global__ void segmax_kernel(const int* __restrict__ dst, const float* __restrict__ logits,
                              unsigned* __restrict__ umax, int E)
{
    int t = blockIdx.x * blockDim.x + threadIdx.x;
    if (t >= E * NH) return;
    int e = t / NH, h = t - e * NH;
    float p = logits[t];
    unsigned u = __float_as_uint(p);
    u ^= (u >> 31) ? 0xFFFFFFFFu : 0x80000000u;
    atomicMax(&umax[dst[e] * NH + h], u);
}

// ---------------- exp + denominator ----------------
__global__ void expsum_kernel(const int* __restrict__ dst, float* __restrict__ logits,
                              const unsigned* __restrict__ umax, float* __restrict__ den, int E)
{
    int t = blockIdx.x * blockDim.x + threadIdx.x;
    if (t >= E * NH) return;
    int e = t / NH, h = t - e * NH;
    int d = dst[e];
    unsigned u = umax[d * NH + h];
    float m = (u & 0x80000000u) ? __uint_as_float(u ^ 0x80000000u) : __uint_as_float(~u);
    float ex = expf(logits[t] - m);
    logits[t] = ex;
    atomicAdd(&den[d * NH + h], ex);
}

// ---------------- aggregate ----------------
__global__ void agg_kernel(const int* __restrict__ src, const int* __restrict__ dst,
                           const float* __restrict__ ex, const float* __restrict__ den,
                           const float* __restrict__ xl, float* __restrict__ hmean, int E)
{
    int e    = (blockIdx.x * blockDim.x + threadIdx.x) >> 5;
    int lane = threadIdx.x & 31;
    if (e >= E) return;
    int s = src[e], d = dst[e];
    float a = 0.f;
    if (lane < NH) a = ex[e * NH + lane] / (den[d * NH + lane] + 1e-16f);
    float alpha[NH];
#pragma unroll
    for (int h = 0; h < NH; h++) alpha[h] = __shfl_sync(0xffffffffu, a, h);
    const float* xls = xl + (size_t)s * HC;
#pragma unroll
    for (int j = 0; j < 3; j++) {
        int c = lane + 32 * j;
        float v = 0.f;
#pragma unroll
        for (int h = 0; h < NH; h++) v = fmaf(alpha[h], xls[h * 96 + c], v);
        atomicAdd(&hmean[(size_t)d * HID + c], v * (1.f / 6.f));
    }
}

// ---------------- node update ----------------
__global__ void nodeupd_kernel(const float* __restrict__ cb, const float* __restrict__ g,
                               const float* __restrict__ bt, int doElu,
                               const float* __restrict__ hmean, float* __restrict__ x, int M)
{
    int n    = (blockIdx.x * blockDim.x + threadIdx.x) >> 5;
    int lane = threadIdx.x & 31;
    if (n >= M) return;
    float v[3];
#pragma unroll
    for (int j = 0; j < 3; j++) {
        int c = lane + 32 * j;
        float hv = hmean[(size_t)n * HID + c] + cb[c];
        if (doElu) hv = (hv > 0.f) ? hv : (expf(hv) - 1.f);
        v[j] = hv;
    }
    float mu = warpsum32(v[0] + v[1] + v[2]) * (1.f / 96.f);
    float q = 0.f;
#pragma unroll
    for (int j = 0; j < 3; j++) { float d = v[j] - mu; q = fmaf(d, d, q); }
    float rstd = rsqrtf(warpsum32(q) * (1.f / 96.f) + 1e-5f);
#pragma unroll
    for (int j = 0; j < 3; j++) {
        int c = lane + 32 * j;
        float y = (v[j] - mu) * rstd * g[c] + bt[c];
        x[(size_t)n * HID + c] += y;
    }
}

// ---------------- fused predictor MLP ----------------
#define S_P1W 36864
#define S_P2W 8192
#define S_P3W 64
#define S_C1  384
#define S_C2  192
#define S_CTX 9216
#define PRED_SMEM ((S_P1W + S_P2W + S_P3W + S_C1 + S_C2 + S_CTX) * 4)

__global__ __launch_bounds__(256) void predictor_kernel(
    const int* __restrict__ src, const int* __restrict__ dst,
    const float* __restrict__ xnode, const float* __restrict__ eemb,
    const float* __restrict__ p1w, const float* __restrict__ p1b,
    const float* __restrict__ p1g, const float* __restrict__ p1bt,
    const float* __restrict__ p2w, const float* __restrict__ p2b,
    const float* __restrict__ p2g, const float* __restrict__ p2bt,
    const float* __restrict__ p3w, const float* __restrict__ p3b,
    float* __restrict__ out, int E)
{
    extern __shared__ float sm[];
    float* s_p1w = sm;
    float* s_p2w = s_p1w + S_P1W;
    float* s_p3w = s_p2w + S_P2W;
    float* s_c1  = s_p3w + S_P3W;
    float* s_c2  = s_c1 + S_C1;
    float* s_ctx = s_c2 + S_C2;

    int tid = threadIdx.x;
    for (int i = tid; i < S_P1W / 4; i += 256) ((float4*)s_p1w)[i] = ((const float4*)p1w)[i];
    for (int i = tid; i < S_P2W / 4; i += 256) ((float4*)s_p2w)[i] = ((const float4*)p2w)[i];
    if (tid < 64) s_p3w[tid] = p3w[tid];
    if (tid < 128) { s_c1[tid] = p1b[tid]; s_c1[128 + tid] = p1g[tid]; s_c1[256 + tid] = p1bt[tid]; }
    if (tid < 64)  { s_c2[tid] = p2b[tid]; s_c2[64 + tid]  = p2g[tid]; s_c2[128 + tid] = p2bt[tid]; }

    int eb = blockIdx.x * 32;
    for (int i = tid; i < 32 * 288; i += 256) {
        int el = i / 288, k = i - el * 288;
        int e = eb + el; if (e > E - 1) e = E - 1;
        float v;
        if (k < 96)       v = xnode[(size_t)src[e] * HID + k];
        else if (k < 192) v = xnode[(size_t)dst[e] * HID + (k - 96)];
        else              v = eemb[(size_t)e * HID + (k - 192)];
        s_ctx[el * 288 + k] = v;
    }
    __syncthreads();

    int p = tid >> 4, jg = tid & 15;
    int el0 = 2 * p, el1 = 2 * p + 1;
    const float* c0 = s_ctx + el0 * 288;
    const float* c1 = s_ctx + el1 * 288;

    int jA = jg * 4, jB = 64 + jg * 4;
    ull H0A0 = 0, H0A1 = 0, H0B0 = 0, H0B1 = 0;
    ull H1A0 = 0, H1A1 = 0, H1B0 = 0, H1B1 = 0;
    for (int k = 0; k < 288; k++) {
        float a0 = c0[k], a1 = c1[k];
        ull a0d, a1d;
        asm("mov.b64 %0, {%1, %1};" : "=l"(a0d) : "f"(a0));
        asm("mov.b64 %0, {%1, %1};" : "=l"(a1d) : "f"(a1));
        ulonglong2 wa = *(const ulonglong2*)(s_p1w + k * 128 + jA);
        ulonglong2 wb = *(const ulonglong2*)(s_p1w + k * 128 + jB);
        H0A0 = fma2(a0d, wa.x, H0A0); H0A1 = fma2(a0d, wa.y, H0A1);
        H0B0 = fma2(a0d, wb.x, H0B0); H0B1 = fma2(a0d, wb.y, H0B1);
        H1A0 = fma2(a1d, wa.x, H1A0); H1A1 = fma2(a1d, wa.y, H1A1);
        H1B0 = fma2(a1d, wb.x, H1B0); H1B1 = fma2(a1d, wb.y, H1B1);
    }
    float h0a[4], h0b[4], h1a[4], h1b[4];
    { float2 u;
      u = unpack2(H0A0); h0a[0] = u.x; h0a[1] = u.y;
      u = unpack2(H0A1); h0a[2] = u.x; h0a[3] = u.y;
      u = unpack2(H0B0); h0b[0] = u.x; h0b[1] = u.y;
      u = unpack2(H0B1); h0b[2] = u.x; h0b[3] = u.y;
      u = unpack2(H1A0); h1a[0] = u.x; h1a[1] = u.y;
      u = unpack2(H1A1); h1a[2] = u.x; h1a[3] = u.y;
      u = unpack2(H1B0); h1b[0] = u.x; h1b[1] = u.y;
      u = unpack2(H1B1); h1b[2] = u.x; h1b[3] = u.y; }
#pragma unroll
    for (int i = 0; i < 4; i++) {
        h0a[i] += s_c1[jA + i]; h0b[i] += s_c1[jB + i];
        h1a[i] += s_c1[jA + i]; h1b[i] += s_c1[jB + i];
    }
    {
        float s0 = 0, s1 = 0;
#pragma unroll
        for (int i = 0; i < 4; i++) { s0 += h0a[i] + h0b[i]; s1 += h1a[i] + h1b[i]; }
        float mu0 = gsum16(s0) * (1.f / 128.f), mu1 = gsum16(s1) * (1.f / 128.f);
        float q0 = 0, q1 = 0;
#pragma unroll
        for (int i = 0; i < 4; i++) {
            float d; d = h0a[i] - mu0; q0 = fmaf(d, d, q0); d = h0b[i] - mu0; q0 = fmaf(d, d, q0);
            d = h1a[i] - mu1; q1 = fmaf(d, d, q1); d = h1b[i] - mu1; q1 = fmaf(d, d, q1);
        }
        float r0 = rsqrtf(gsum16(q0) * (1.f / 128.f) + 1e-5f);
        float r1 = rsqrtf(gsum16(q1) * (1.f / 128.f) + 1e-5f);
#pragma unroll
        for (int i = 0; i < 4; i++) {
            h0a[i] = fmaxf((h0a[i] - mu0) * r0 * s_c1[128 + jA + i] + s_c1[256 + jA + i], 0.f);
            h0b[i] = fmaxf((h0b[i] - mu0) * r0 * s_c1[128 + jB + i] + s_c1[256 + jB + i], 0.f);
            h1a[i] = fmaxf((h1a[i] - mu1) * r1 * s_c1[128 + jA + i] + s_c1[256 + jA + i], 0.f);
            h1b[i] = fmaxf((h1b[i] - mu1) * r1 * s_c1[128 + jB + i] + s_c1[256 + jB + i], 0.f);
        }
    }
    __syncthreads();
#pragma unroll
    for (int i = 0; i < 4; i++) {
        s_ctx[el0 * 288 + jA + i] = h0a[i]; s_ctx[el0 * 288 + jB + i] = h0b[i];
        s_ctx[el1 * 288 + jA + i] = h1a[i]; s_ctx[el1 * 288 + jB + i] = h1b[i];
    }
    __syncthreads();

    int j2 = jg * 4;
    ull G00 = 0, G01 = 0, G10 = 0, G11 = 0;
    const float* hh0 = s_ctx + el0 * 288;
    const float* hh1 = s_ctx + el1 * 288;
    for (int k = 0; k < 128; k++) {
        float a0 = hh0[k], a1 = hh1[k];
        ull a0d, a1d;
        asm("mov.b64 %0, {%1, %1};" : "=l"(a0d) : "f"(a0));
        asm("mov.b64 %0, {%1, %1};" : "=l"(a1d) : "f"(a1));
        ulonglong2 w = *(const ulonglong2*)(s_p2w + k * 64 + j2);
        G00 = fma2(a0d, w.x, G00); G01 = fma2(a0d, w.y, G01);
        G10 = fma2(a1d, w.x, G10); G11 = fma2(a1d, w.y, G11);
    }
    float g0[4], g1[4];
    { float2 u;
      u = unpack2(G00); g0[0] = u.x; g0[1] = u.y;
      u = unpack2(G01); g0[2] = u.x; g0[3] = u.y;
      u = unpack2(G10); g1[0] = u.x; g1[1] = u.y;
      u = unpack2(G11); g1[2] = u.x; g1[3] = u.y; }
#pragma unroll
    for (int i = 0; i < 4; i++) { g0[i] += s_c2[j2 + i]; g1[i] += s_c2[j2 + i]; }
    {
        float s0 = 0, s1 = 0;
#pragma unroll
        for (int i = 0; i < 4; i++) { s0 += g0[i]; s1 += g1[i]; }
        float mu0 = gsum16(s0) * (1.f / 64.f), mu1 = gsum16(s1) * (1.f / 64.f);
        float q0 = 0, q1 = 0;
#pragma unroll
        for (int i = 0; i < 4; i++) {
            float d; d = g0[i] - mu0; q0 = fmaf(d, d, q0);
            d = g1[i] - mu1; q1 = fmaf(d, d, q1);
        }
        float r0 = rsqrtf(gsum16(q0) * (1.f / 64.f) + 1e-5f);
        float r1 = rsqrtf(gsum16(q1) * (1.f / 64.f) + 1e-5f);
#pragma unroll
        for (int i = 0; i < 4; i++) {
            g0[i] = fmaxf((g0[i] - mu0) * r0 * s_c2[64 + j2 + i] + s_c2[128 + j2 + i], 0.f);
            g1[i] = fmaxf((g1[i] - mu1) * r1 * s_c2[64 + j2 + i] + s_c2[128 + j2 + i], 0.f);
        }
    }
    float o0 = 0, o1 = 0;
#pragma unroll
    for (int i = 0; i < 4; i++) {
        o0 = fmaf(g0[i], s_p3w[j2 + i], o0);
        o1 = fmaf(g1[i], s_p3w[j2 + i], o1);
    }
    o0 = gsum16(o0); o1 = gsum16(o1);
    if (jg == 0) {
        float pb = p3b[0];
        int e0 = eb + el0, e1 = eb + el1;
        if (e0 < E) out[e0] = o0 + pb;
        if (e1 < E) out[e1] = o1 + pb;
    }
}

// ---------------- launch ----------------
extern "C" void kernel_launch(void* const* d_in, const int* in_sizes, int n_in,
                              void* d_out, int out_size)
{
    const float* x         = (const float*)d_in[0];
    const float* edge_attr = (const float*)d_in[1];
    const int*   edge_idx  = (const int*)d_in[2];
    const float* ne_w = (const float*)d_in[3];
    const float* ne_b = (const float*)d_in[4];
    const float* ne_g = (const float*)d_in[5];
    const float* ne_bt = (const float*)d_in[6];
    const float* ee_w = (const float*)d_in[7];
    const float* ee_b = (const float*)d_in[8];
    const float* ee_g = (const float*)d_in[9];
    const float* ee_bt = (const float*)d_in[10];
    const float* Wl = (const float*)d_in[11];
    const float* bl = (const float*)d_in[12];
    const float* Wr = (const float*)d_in[13];
    const float* br = (const float*)d_in[14];
    const float* We = (const float*)d_in[15];
    const float* attw = (const float*)d_in[16];
    const float* cbias = (const float*)d_in[17];
    const float* lng = (const float*)d_in[18];
    const float* lnb = (const float*)d_in[19];
    const float* p1w = (const float*)d_in[20];
    const float* p1b = (const float*)d_in[21];
    const float* p1g = (const float*)d_in[22];
    const float* p1bt = (const float*)d_in[23];
    const float* p2w = (const float*)d_in[24];
    const float* p2b = (const float*)d_in[25];
    const float* p2g = (const float*)d_in[26];
    const float* p2bt = (const float*)d_in[27];
    const float* p3w = (const float*)d_in[28];
    const float* p3b = (const float*)d_in[29];

    int Nn = in_sizes[0] / 4;
    int E  = in_sizes[1] / 3;
    const int* srcp = edge_idx;
    const int* dstp = edge_idx + E;
    float* outp = (float*)d_out;

    void *px_, *pe_, *pxl_, *pxr_, *plog_, *pumax_, *pden_, *phm_;
    cudaGetSymbolAddress(&px_, g_x);
    cudaGetSymbolAddress(&pe_, g_eemb);
    cudaGetSymbolAddress(&pxl_, g_xl);
    cudaGetSymbolAddress(&pxr_, g_xr);
    cudaGetSymbolAddress(&plog_, g_logits);
    cudaGetSymbolAddress(&pumax_, g_umax);
    cudaGetSymbolAddress(&pden_, g_den);
    cudaGetSymbolAddress(&phm_, g_hmean);
    float* px = (float*)px_;   float* pe = (float*)pe_;
    float* pxl = (float*)pxl_; float* pxr = (float*)pxr_;
    float* plog = (float*)plog_;
    unsigned* pumax = (unsigned*)pumax_;
    float* pden = (float*)pden_; float* phm = (float*)phm_;

    cudaFuncSetAttribute(gemm96_kernel<false>,
                         cudaFuncAttributeMaxDynamicSharedMemorySize, GEMM_SMEM);
    cudaFuncSetAttribute(gemm96_kernel<true>,
                         cudaFuncAttributeMaxDynamicSharedMemorySize, GEMM_SMEM);
    cudaFuncSetAttribute(predictor_kernel,
                         cudaFuncAttributeMaxDynamicSharedMemorySize, PRED_SMEM);

    encoder_kernel<<<(Nn + 7) / 8, 256>>>(x, 4, ne_w, ne_b, ne_g, ne_bt, px, Nn);
    encoder_kernel<<<(E + 7) / 8, 256>>>(edge_attr, 3, ee_w, ee_b, ee_g, ee_bt, pe, E);

    dim3 gN((Nn + BM - 1) / BM, HC / BN);
    dim3 gE((E + BM - 1) / BM, HC / BN);

    for (int l = 0; l < 3; l++) {
        const float* Wl_l = Wl + (size_t)l * 96 * HC;
        const float* Wr_l = Wr + (size_t)l * 96 * HC;
        const float* We_l = We + (size_t)l * 96 * HC;
        gemm96_kernel<false><<<gN, 256, GEMM_SMEM>>>(px, Wl_l, bl + l * HC, pxl, Nn,
                                                     0, 0, 0, 0, 0, 0);
        gemm96_kernel<false><<<gN, 256, GEMM_SMEM>>>(px, Wr_l, br + l * HC, pxr, Nn,
                                                     0, 0, 0, 0, 0, 0);

        cudaMemsetAsync(plog, 0, (size_t)E * NH * sizeof(float), 0);
        cudaMemsetAsync(pumax, 0, (size_t)Nn * NH * sizeof(unsigned), 0);
        cudaMemsetAsync(pden, 0, (size_t)Nn * NH * sizeof(float), 0);
        cudaMemsetAsync(phm, 0, (size_t)Nn * HID * sizeof(float), 0);

        gemm96_kernel<true><<<gE, 256, GEMM_SMEM>>>(pe, We_l, (const float*)0, (float*)0, E,
                                                    srcp, dstp, pxl, pxr,
                                                    attw + l * NH * 96, plog);

        segmax_kernel<<<(E * NH + 255) / 256, 256>>>(dstp, plog, pumax, E);
        expsum_kernel<<<(E * NH + 255) / 256, 256>>>(dstp, plog, pumax, pden, E);
        agg_kernel<<<(E + 7) / 8, 256>>>(srcp, dstp, plog, pden, pxl, phm, E);
        nodeupd_kernel<<<(Nn + 7) / 8, 256>>>(cbias + l * HID, lng + l * HID,
                                              lnb + l * HID, (l < 2) ? 1 : 0, phm, px, Nn);
    }

    predictor_kernel<<<(E + 31) / 32, 256, PRED_SMEM>>>(
        srcp, dstp, px, pe,
        p1w, p1b, p1g, p1bt, p2w, p2b, p2g, p2bt, p3w, p3b, outp, E);
}

// round 5
// speedup vs baseline: 1.5111x; 1.5111x over previous
#include <cuda_runtime.h>
#include <math.h>

#define HID 96
#define HC  576
#define NH  6

typedef unsigned long long ull;

// ---------------- f32x2 packed helpers ----------------
__device__ __forceinline__ ull fma2(ull a, ull b, ull c) {
    ull d;
    asm("fma.rn.f32x2 %0, %1, %2, %3;" : "=l"(d) : "l"(a), "l"(b), "l"(c));
    return d;
}
__device__ __forceinline__ ull pack2(float x, float y) {
    ull r;
    asm("mov.b64 %0, {%1, %2};" : "=l"(r) : "f"(x), "f"(y));
    return r;
}
__device__ __forceinline__ ull dup2(float x) { return pack2(x, x); }
__device__ __forceinline__ float2 unpack2(ull v) {
    float2 r;
    asm("mov.b64 {%0, %1}, %2;" : "=f"(r.x), "=f"(r.y) : "l"(v));
    return r;
}
__device__ __forceinline__ unsigned f2tf32(float f) {
    unsigned r;
    asm("cvt.rna.tf32.f32 %0, %1;" : "=r"(r) : "f"(f));
    return r;
}
__device__ __forceinline__ void mma_tf32(float c[4],
    unsigned a0, unsigned a1, unsigned a2, unsigned a3,
    unsigned b0, unsigned b1)
{
    asm("mma.sync.aligned.m16n8k8.row.col.f32.tf32.tf32.f32 "
        "{%0,%1,%2,%3},{%4,%5,%6,%7},{%8,%9},{%0,%1,%2,%3};"
        : "+f"(c[0]), "+f"(c[1]), "+f"(c[2]), "+f"(c[3])
        : "r"(a0), "r"(a1), "r"(a2), "r"(a3), "r"(b0), "r"(b1));
}

// ---------------- scratch ----------------
__device__ float    g_x[20000 * HID];
__device__ float    g_eemb[200000 * HID];
__device__ float    g_xl[20000 * HC];
__device__ float    g_xr[20000 * HC];
__device__ float    g_logits[200000 * NH];
__device__ unsigned g_umax[20000 * NH];
__device__ float    g_den[20000 * NH];
__device__ float    g_hmean[20000 * HID];

__device__ __forceinline__ float warpsum32(float v) {
#pragma unroll
    for (int m = 16; m; m >>= 1) v += __shfl_xor_sync(0xffffffffu, v, m);
    return v;
}
__device__ __forceinline__ float gsum16(float v) {
#pragma unroll
    for (int m = 8; m; m >>= 1) v += __shfl_xor_sync(0xffffffffu, v, m);
    return v;
}

// ---------------- encoder ----------------
__global__ void encoder_kernel(const float* __restrict__ in, int Fin,
                               const float* __restrict__ W, const float* __restrict__ b,
                               const float* __restrict__ g, const float* __restrict__ beta,
                               float* __restrict__ out, int M)
{
    int w    = (blockIdx.x * blockDim.x + threadIdx.x) >> 5;
    int lane = threadIdx.x & 31;
    if (w >= M) return;
    float xin[4];
#pragma unroll
    for (int k = 0; k < 4; k++) xin[k] = (k < Fin) ? in[(size_t)w * Fin + k] : 0.f;
    float v[3];
#pragma unroll
    for (int j = 0; j < 3; j++) {
        int c = lane + 32 * j;
        float acc = b[c];
        for (int k = 0; k < Fin; k++) acc = fmaf(xin[k], W[k * HID + c], acc);
        v[j] = acc;
    }
    float mu = warpsum32(v[0] + v[1] + v[2]) * (1.f / 96.f);
    float q = 0.f;
#pragma unroll
    for (int j = 0; j < 3; j++) { float d = v[j] - mu; q = fmaf(d, d, q); }
    float rstd = rsqrtf(warpsum32(q) * (1.f / 96.f) + 1e-5f);
#pragma unroll
    for (int j = 0; j < 3; j++) {
        int c = lane + 32 * j;
        float y = (v[j] - mu) * rstd * g[c] + beta[c];
        out[(size_t)w * HID + c] = fmaxf(y, 0.f);
    }
}

// ---------------- node GEMM (R2-measured config, fp32 f32x2) ----------------
#define BM 128
#define BN 64
#define BK 32
#define PAD_AS 132

__global__ __launch_bounds__(256) void gemm96_kernel(
    const float* __restrict__ A, const float* __restrict__ B,
    const float* __restrict__ bias, float* __restrict__ C, int M)
{
    __shared__ float As[BK * PAD_AS];
    __shared__ float Bs[BK * BN];
    int tid = threadIdx.x;
    int m0 = blockIdx.x * BM, n0 = blockIdx.y * BN;
    int tx = tid & 15, ty = tid >> 4;

    ull acc2[4][4];
#pragma unroll
    for (int p = 0; p < 4; p++)
#pragma unroll
        for (int j = 0; j < 4; j++) acc2[p][j] = 0ull;

    for (int k0 = 0; k0 < 96; k0 += BK) {
#pragma unroll
        for (int r = 0; r < 4; r++) {
            int row = (tid >> 3) + r * 32;
            int kq  = (tid & 7) * 4;
            int m   = m0 + row;
            float4 av = make_float4(0.f, 0.f, 0.f, 0.f);
            if (m < M) av = *(const float4*)(A + (size_t)m * 96 + k0 + kq);
            As[(kq + 0) * PAD_AS + row] = av.x;
            As[(kq + 1) * PAD_AS + row] = av.y;
            As[(kq + 2) * PAD_AS + row] = av.z;
            As[(kq + 3) * PAD_AS + row] = av.w;
        }
#pragma unroll
        for (int r = 0; r < 2; r++) {
            int kr = (tid >> 4) + r * 16;
            int nq = (tid & 15) * 4;
            *(float4*)(Bs + kr * BN + nq) =
                *(const float4*)(B + (size_t)(k0 + kr) * HC + n0 + nq);
        }
        __syncthreads();
#pragma unroll
        for (int k = 0; k < BK; k++) {
            float4 a0 = *(float4*)(As + k * PAD_AS + ty * 8);
            float4 a1 = *(float4*)(As + k * PAD_AS + ty * 8 + 4);
            float4 bb = *(float4*)(Bs + k * BN + tx * 4);
            ull ap[4] = {pack2(a0.x, a0.y), pack2(a0.z, a0.w),
                         pack2(a1.x, a1.y), pack2(a1.z, a1.w)};
            ull bd[4] = {dup2(bb.x), dup2(bb.y), dup2(bb.z), dup2(bb.w)};
#pragma unroll
            for (int p = 0; p < 4; p++)
#pragma unroll
                for (int j = 0; j < 4; j++)
                    acc2[p][j] = fma2(ap[p], bd[j], acc2[p][j]);
        }
        __syncthreads();
    }

    float accf[8][4];
#pragma unroll
    for (int p = 0; p < 4; p++)
#pragma unroll
        for (int j = 0; j < 4; j++) {
            float2 u = unpack2(acc2[p][j]);
            accf[2 * p][j]     = u.x;
            accf[2 * p + 1][j] = u.y;
        }

    float4 bq = make_float4(0.f, 0.f, 0.f, 0.f);
    if (bias) bq = *(const float4*)(bias + n0 + tx * 4);
#pragma unroll
    for (int i = 0; i < 8; i++) {
        int m = m0 + ty * 8 + i;
        if (m < M) {
            float4 o = make_float4(accf[i][0] + bq.x, accf[i][1] + bq.y,
                                   accf[i][2] + bq.z, accf[i][3] + bq.w);
            *(float4*)(C + (size_t)m * HC + n0 + tx * 4) = o;
        }
    }
}

// ---------------- edge GEMM (tf32 mma) + fused GATv2 logit partials ----------------
// tile 128x64, 8 warps (4m x 2n), each warp 32x32 via m16n8k8 tf32 mma.
// K = 96 staged once in smem (tf32), fp32 accumulation.
#define PAD_A 136
#define PAD_B 72
#define TF_SMEM ((96 * PAD_A + 96 * PAD_B) * 4)

__global__ __launch_bounds__(256) void edge_tf32_kernel(
    const float* __restrict__ Ag, const float* __restrict__ Bg, int M,
    const int* __restrict__ src, const int* __restrict__ dst,
    const float* __restrict__ xl, const float* __restrict__ xr,
    const float* __restrict__ attw, float* __restrict__ logits)
{
    extern __shared__ unsigned sh_u[];
    unsigned* As = sh_u;                 // [96][PAD_A]  k-major (transposed)
    unsigned* Bs = sh_u + 96 * PAD_A;    // [96][PAD_B]

    int tid = threadIdx.x;
    int m0 = blockIdx.x * 128, n0 = blockIdx.y * 64;

    // stage A: convert to tf32 + transpose
    {
        int row   = tid >> 1;
        int kbase = (tid & 1) * 48;
        int m     = m0 + row;
#pragma unroll
        for (int i = 0; i < 12; i++) {
            float4 v = make_float4(0.f, 0.f, 0.f, 0.f);
            if (m < M) v = *(const float4*)(Ag + (size_t)m * 96 + kbase + i * 4);
            int k = kbase + i * 4;
            As[(k + 0) * PAD_A + row] = f2tf32(v.x);
            As[(k + 1) * PAD_A + row] = f2tf32(v.y);
            As[(k + 2) * PAD_A + row] = f2tf32(v.z);
            As[(k + 3) * PAD_A + row] = f2tf32(v.w);
        }
    }
    // stage B: convert to tf32
#pragma unroll
    for (int i = 0; i < 6; i++) {
        int lin = tid + 256 * i;         // 0..1535 over 96 rows x 16 float4
        int kr = lin >> 4, nq = (lin & 15) * 4;
        float4 v = *(const float4*)(Bg + (size_t)kr * HC + n0 + nq);
        uint4 o = make_uint4(f2tf32(v.x), f2tf32(v.y), f2tf32(v.z), f2tf32(v.w));
        *(uint4*)(Bs + kr * PAD_B + nq) = o;
    }
    __syncthreads();

    int wid = tid >> 5, lane = tid & 31;
    int wm = wid & 3, wn = wid >> 2;     // warp tile: rows wm*32, cols wn*32
    int g = lane >> 2, tig = lane & 3;
    int rowb = wm * 32;
    int colb = wn * 32;

    float acc[2][4][4];
#pragma unroll
    for (int mt = 0; mt < 2; mt++)
#pragma unroll
        for (int nt = 0; nt < 4; nt++)
#pragma unroll
            for (int q = 0; q < 4; q++) acc[mt][nt][q] = 0.f;

#pragma unroll
    for (int ks = 0; ks < 12; ks++) {
        int k0 = ks * 8;
        unsigned a[2][4];
#pragma unroll
        for (int mt = 0; mt < 2; mt++) {
            int rb = rowb + mt * 16 + g;
            a[mt][0] = As[(k0 + tig) * PAD_A + rb];
            a[mt][1] = As[(k0 + tig) * PAD_A + rb + 8];
            a[mt][2] = As[(k0 + tig + 4) * PAD_A + rb];
            a[mt][3] = As[(k0 + tig + 4) * PAD_A + rb + 8];
        }
        unsigned bf[4][2];
#pragma unroll
        for (int nt = 0; nt < 4; nt++) {
            int cb = colb + nt * 8 + g;
            bf[nt][0] = Bs[(k0 + tig) * PAD_B + cb];
            bf[nt][1] = Bs[(k0 + tig + 4) * PAD_B + cb];
        }
#pragma unroll
        for (int mt = 0; mt < 2; mt++)
#pragma unroll
            for (int nt = 0; nt < 4; nt++)
                mma_tf32(acc[mt][nt], a[mt][0], a[mt][1], a[mt][2], a[mt][3],
                         bf[nt][0], bf[nt][1]);
    }

    // fused GATv2 logit epilogue. warp covers 32 contiguous cols -> single head.
    int h = (n0 + colb) / 96;
#pragma unroll
    for (int mt = 0; mt < 2; mt++) {
#pragma unroll
        for (int half = 0; half < 2; half++) {
            int m = m0 + rowb + mt * 16 + half * 8 + g;
            float partial = 0.f;
            if (m < M) {
                int s = src[m], d = dst[m];
                const float* xls = xl + (size_t)s * HC;
                const float* xrd = xr + (size_t)d * HC;
#pragma unroll
                for (int nt = 0; nt < 4; nt++) {
                    int c = n0 + colb + nt * 8 + 2 * tig;
                    float2 xlv = *(const float2*)(xls + c);
                    float2 xrv = *(const float2*)(xrd + c);
                    float aw0 = attw[c], aw1 = attw[c + 1];
                    float a0 = acc[mt][nt][half * 2 + 0];
                    float a1 = acc[mt][nt][half * 2 + 1];
                    float t0 = a0 + xlv.x + xrv.x; t0 = (t0 > 0.f) ? t0 : 0.2f * t0;
                    float t1 = a1 + xlv.y + xrv.y; t1 = (t1 > 0.f) ? t1 : 0.2f * t1;
                    partial = fmaf(t0, aw0, fmaf(t1, aw1, partial));
                }
            }
            partial += __shfl_down_sync(0xffffffffu, partial, 1, 4);
            partial += __shfl_down_sync(0xffffffffu, partial, 2, 4);
            if (tig == 0 && m < M)
                atomicAdd(&logits[(size_t)m * NH + h], partial);
        }
    }
}

// ---------------- segment max ----------------
__global__ void segmax_kernel(const int* __restrict__ dst, const float* __restrict__ logits,
                              unsigned* __restrict__ umax, int E)
{
    int t = blockIdx.x * blockDim.x + threadIdx.x;
    if (t >= E * NH) return;
    int e = t / NH, h = t - e * NH;
    float p = logits[t];
    unsigned u = __float_as_uint(p);
    u ^= (u >> 31) ? 0xFFFFFFFFu : 0x80000000u;
    atomicMax(&umax[dst[e] * NH + h], u);
}

// ---------------- exp + denominator ----------------
__global__ void expsum_kernel(const int* __restrict__ dst, float* __restrict__ logits,
                              const unsigned* __restrict__ umax, float* __restrict__ den, int E)
{
    int t = blockIdx.x * blockDim.x + threadIdx.x;
    if (t >= E * NH) return;
    int e = t / NH, h = t - e * NH;
    int d = dst[e];
    unsigned u = umax[d * NH + h];
    float m = (u & 0x80000000u) ? __uint_as_float(u ^ 0x80000000u) : __uint_as_float(~u);
    float ex = expf(logits[t] - m);
    logits[t] = ex;
    atomicAdd(&den[d * NH + h], ex);
}

// ---------------- aggregate ----------------
__global__ void agg_kernel(const int* __restrict__ src, const int* __restrict__ dst,
                           const float* __restrict__ ex, const float* __restrict__ den,
                           const float* __restrict__ xl, float* __restrict__ hmean, int E)
{
    int e    = (blockIdx.x * blockDim.x + threadIdx.x) >> 5;
    int lane = threadIdx.x & 31;
    if (e >= E) return;
    int s = src[e], d = dst[e];
    float a = 0.f;
    if (lane < NH) a = ex[e * NH + lane] / (den[d * NH + lane] + 1e-16f);
    float alpha[NH];
#pragma unroll
    for (int h = 0; h < NH; h++) alpha[h] = __shfl_sync(0xffffffffu, a, h);
    const float* xls = xl + (size_t)s * HC;
#pragma unroll
    for (int j = 0; j < 3; j++) {
        int c = lane + 32 * j;
        float v = 0.f;
#pragma unroll
        for (int h = 0; h < NH; h++) v = fmaf(alpha[h], xls[h * 96 + c], v);
        atomicAdd(&hmean[(size_t)d * HID + c], v * (1.f / 6.f));
    }
}

// ---------------- node update ----------------
__global__ void nodeupd_kernel(const float* __restrict__ cb, const float* __restrict__ g,
                               const float* __restrict__ bt, int doElu,
                               const float* __restrict__ hmean, float* __restrict__ x, int M)
{
    int n    = (blockIdx.x * blockDim.x + threadIdx.x) >> 5;
    int lane = threadIdx.x & 31;
    if (n >= M) return;
    float v[3];
#pragma unroll
    for (int j = 0; j < 3; j++) {
        int c = lane + 32 * j;
        float hv = hmean[(size_t)n * HID + c] + cb[c];
        if (doElu) hv = (hv > 0.f) ? hv : (expf(hv) - 1.f);
        v[j] = hv;
    }
    float mu = warpsum32(v[0] + v[1] + v[2]) * (1.f / 96.f);
    float q = 0.f;
#pragma unroll
    for (int j = 0; j < 3; j++) { float d = v[j] - mu; q = fmaf(d, d, q); }
    float rstd = rsqrtf(warpsum32(q) * (1.f / 96.f) + 1e-5f);
#pragma unroll
    for (int j = 0; j < 3; j++) {
        int c = lane + 32 * j;
        float y = (v[j] - mu) * rstd * g[c] + bt[c];
        x[(size_t)n * HID + c] += y;
    }
}

// ---------------- fused predictor MLP ----------------
#define S_P1W 36864
#define S_P2W 8192
#define S_P3W 64
#define S_C1  384
#define S_C2  192
#define S_CTX 9216
#define PRED_SMEM ((S_P1W + S_P2W + S_P3W + S_C1 + S_C2 + S_CTX) * 4)

__global__ __launch_bounds__(256) void predictor_kernel(
    const int* __restrict__ src, const int* __restrict__ dst,
    const float* __restrict__ xnode, const float* __restrict__ eemb,
    const float* __restrict__ p1w, const float* __restrict__ p1b,
    const float* __restrict__ p1g, const float* __restrict__ p1bt,
    const float* __restrict__ p2w, const float* __restrict__ p2b,
    const float* __restrict__ p2g, const float* __restrict__ p2bt,
    const float* __restrict__ p3w, const float* __restrict__ p3b,
    float* __restrict__ out, int E)
{
    extern __shared__ float sm[];
    float* s_p1w = sm;
    float* s_p2w = s_p1w + S_P1W;
    float* s_p3w = s_p2w + S_P2W;
    float* s_c1  = s_p3w + S_P3W;
    float* s_c2  = s_c1 + S_C1;
    float* s_ctx = s_c2 + S_C2;

    int tid = threadIdx.x;
    for (int i = tid; i < S_P1W / 4; i += 256) ((float4*)s_p1w)[i] = ((const float4*)p1w)[i];
    for (int i = tid; i < S_P2W / 4; i += 256) ((float4*)s_p2w)[i] = ((const float4*)p2w)[i];
    if (tid < 64) s_p3w[tid] = p3w[tid];
    if (tid < 128) { s_c1[tid] = p1b[tid]; s_c1[128 + tid] = p1g[tid]; s_c1[256 + tid] = p1bt[tid]; }
    if (tid < 64)  { s_c2[tid] = p2b[tid]; s_c2[64 + tid]  = p2g[tid]; s_c2[128 + tid] = p2bt[tid]; }

    int eb = blockIdx.x * 32;
    for (int i = tid; i < 32 * 288; i += 256) {
        int el = i / 288, k = i - el * 288;
        int e = eb + el; if (e > E - 1) e = E - 1;
        float v;
        if (k < 96)       v = xnode[(size_t)src[e] * HID + k];
        else if (k < 192) v = xnode[(size_t)dst[e] * HID + (k - 96)];
        else              v = eemb[(size_t)e * HID + (k - 192)];
        s_ctx[el * 288 + k] = v;
    }
    __syncthreads();

    int p = tid >> 4, jg = tid & 15;
    int el0 = 2 * p, el1 = 2 * p + 1;
    const float* c0 = s_ctx + el0 * 288;
    const float* c1 = s_ctx + el1 * 288;

    int jA = jg * 4, jB = 64 + jg * 4;
    ull H0A0 = 0, H0A1 = 0, H0B0 = 0, H0B1 = 0;
    ull H1A0 = 0, H1A1 = 0, H1B0 = 0, H1B1 = 0;
    for (int k = 0; k < 288; k++) {
        float a0 = c0[k], a1 = c1[k];
        ull a0d, a1d;
        asm("mov.b64 %0, {%1, %1};" : "=l"(a0d) : "f"(a0));
        asm("mov.b64 %0, {%1, %1};" : "=l"(a1d) : "f"(a1));
        ulonglong2 wa = *(const ulonglong2*)(s_p1w + k * 128 + jA);
        ulonglong2 wb = *(const ulonglong2*)(s_p1w + k * 128 + jB);
        H0A0 = fma2(a0d, wa.x, H0A0); H0A1 = fma2(a0d, wa.y, H0A1);
        H0B0 = fma2(a0d, wb.x, H0B0); H0B1 = fma2(a0d, wb.y, H0B1);
        H1A0 = fma2(a1d, wa.x, H1A0); H1A1 = fma2(a1d, wa.y, H1A1);
        H1B0 = fma2(a1d, wb.x, H1B0); H1B1 = fma2(a1d, wb.y, H1B1);
    }
    float h0a[4], h0b[4], h1a[4], h1b[4];
    { float2 u;
      u = unpack2(H0A0); h0a[0] = u.x; h0a[1] = u.y;
      u = unpack2(H0A1); h0a[2] = u.x; h0a[3] = u.y;
      u = unpack2(H0B0); h0b[0] = u.x; h0b[1] = u.y;
      u = unpack2(H0B1); h0b[2] = u.x; h0b[3] = u.y;
      u = unpack2(H1A0); h1a[0] = u.x; h1a[1] = u.y;
      u = unpack2(H1A1); h1a[2] = u.x; h1a[3] = u.y;
      u = unpack2(H1B0); h1b[0] = u.x; h1b[1] = u.y;
      u = unpack2(H1B1); h1b[2] = u.x; h1b[3] = u.y; }
#pragma unroll
    for (int i = 0; i < 4; i++) {
        h0a[i] += s_c1[jA + i]; h0b[i] += s_c1[jB + i];
        h1a[i] += s_c1[jA + i]; h1b[i] += s_c1[jB + i];
    }
    {
        float s0 = 0, s1 = 0;
#pragma unroll
        for (int i = 0; i < 4; i++) { s0 += h0a[i] + h0b[i]; s1 += h1a[i] + h1b[i]; }
        float mu0 = gsum16(s0) * (1.f / 128.f), mu1 = gsum16(s1) * (1.f / 128.f);
        float q0 = 0, q1 = 0;
#pragma unroll
        for (int i = 0; i < 4; i++) {
            float d; d = h0a[i] - mu0; q0 = fmaf(d, d, q0); d = h0b[i] - mu0; q0 = fmaf(d, d, q0);
            d = h1a[i] - mu1; q1 = fmaf(d, d, q1); d = h1b[i] - mu1; q1 = fmaf(d, d, q1);
        }
        float r0 = rsqrtf(gsum16(q0) * (1.f / 128.f) + 1e-5f);
        float r1 = rsqrtf(gsum16(q1) * (1.f / 128.f) + 1e-5f);
#pragma unroll
        for (int i = 0; i < 4; i++) {
            h0a[i] = fmaxf((h0a[i] - mu0) * r0 * s_c1[128 + jA + i] + s_c1[256 + jA + i], 0.f);
            h0b[i] = fmaxf((h0b[i] - mu0) * r0 * s_c1[128 + jB + i] + s_c1[256 + jB + i], 0.f);
            h1a[i] = fmaxf((h1a[i] - mu1) * r1 * s_c1[128 + jA + i] + s_c1[256 + jA + i], 0.f);
            h1b[i] = fmaxf((h1b[i] - mu1) * r1 * s_c1[128 + jB + i] + s_c1[256 + jB + i], 0.f);
        }
    }
    __syncthreads();
#pragma unroll
    for (int i = 0; i < 4; i++) {
        s_ctx[el0 * 288 + jA + i] = h0a[i]; s_ctx[el0 * 288 + jB + i] = h0b[i];
        s_ctx[el1 * 288 + jA + i] = h1a[i]; s_ctx[el1 * 288 + jB + i] = h1b[i];
    }
    __syncthreads();

    int j2 = jg * 4;
    ull G00 = 0, G01 = 0, G10 = 0, G11 = 0;
    const float* hh0 = s_ctx + el0 * 288;
    const float* hh1 = s_ctx + el1 * 288;
    for (int k = 0; k < 128; k++) {
        float a0 = hh0[k], a1 = hh1[k];
        ull a0d, a1d;
        asm("mov.b64 %0, {%1, %1};" : "=l"(a0d) : "f"(a0));
        asm("mov.b64 %0, {%1, %1};" : "=l"(a1d) : "f"(a1));
        ulonglong2 w = *(const ulonglong2*)(s_p2w + k * 64 + j2);
        G00 = fma2(a0d, w.x, G00); G01 = fma2(a0d, w.y, G01);
        G10 = fma2(a1d, w.x, G10); G11 = fma2(a1d, w.y, G11);
    }
    float g0[4], g1[4];
    { float2 u;
      u = unpack2(G00); g0[0] = u.x; g0[1] = u.y;
      u = unpack2(G01); g0[2] = u.x; g0[3] = u.y;
      u = unpack2(G10); g1[0] = u.x; g1[1] = u.y;
      u = unpack2(G11); g1[2] = u.x; g1[3] = u.y; }
#pragma unroll
    for (int i = 0; i < 4; i++) { g0[i] += s_c2[j2 + i]; g1[i] += s_c2[j2 + i]; }
    {
        float s0 = 0, s1 = 0;
#pragma unroll
        for (int i = 0; i < 4; i++) { s0 += g0[i]; s1 += g1[i]; }
        float mu0 = gsum16(s0) * (1.f / 64.f), mu1 = gsum16(s1) * (1.f / 64.f);
        float q0 = 0, q1 = 0;
#pragma unroll
        for (int i = 0; i < 4; i++) {
            float d; d = g0[i] - mu0; q0 = fmaf(d, d, q0);
            d = g1[i] - mu1; q1 = fmaf(d, d, q1);
        }
        float r0 = rsqrtf(gsum16(q0) * (1.f / 64.f) + 1e-5f);
        float r1 = rsqrtf(gsum16(q1) * (1.f / 64.f) + 1e-5f);
#pragma unroll
        for (int i = 0; i < 4; i++) {
            g0[i] = fmaxf((g0[i] - mu0) * r0 * s_c2[64 + j2 + i] + s_c2[128 + j2 + i], 0.f);
            g1[i] = fmaxf((g1[i] - mu1) * r1 * s_c2[64 + j2 + i] + s_c2[128 + j2 + i], 0.f);
        }
    }
    float o0 = 0, o1 = 0;
#pragma unroll
    for (int i = 0; i < 4; i++) {
        o0 = fmaf(g0[i], s_p3w[j2 + i], o0);
        o1 = fmaf(g1[i], s_p3w[j2 + i], o1);
    }
    o0 = gsum16(o0); o1 = gsum16(o1);
    if (jg == 0) {
        float pb = p3b[0];
        int e0 = eb + el0, e1 = eb + el1;
        if (e0 < E) out[e0] = o0 + pb;
        if (e1 < E) out[e1] = o1 + pb;
    }
}

// ---------------- launch ----------------
extern "C" void kernel_launch(void* const* d_in, const int* in_sizes, int n_in,
                              void* d_out, int out_size)
{
    const float* x         = (const float*)d_in[0];
    const float* edge_attr = (const float*)d_in[1];
    const int*   edge_idx  = (const int*)d_in[2];
    const float* ne_w = (const float*)d_in[3];
    const float* ne_b = (const float*)d_in[4];
    const float* ne_g = (const float*)d_in[5];
    const float* ne_bt = (const float*)d_in[6];
    const float* ee_w = (const float*)d_in[7];
    const float* ee_b = (const float*)d_in[8];
    const float* ee_g = (const float*)d_in[9];
    const float* ee_bt = (const float*)d_in[10];
    const float* Wl = (const float*)d_in[11];
    const float* bl = (const float*)d_in[12];
    const float* Wr = (const float*)d_in[13];
    const float* br = (const float*)d_in[14];
    const float* We = (const float*)d_in[15];
    const float* attw = (const float*)d_in[16];
    const float* cbias = (const float*)d_in[17];
    const float* lng = (const float*)d_in[18];
    const float* lnb = (const float*)d_in[19];
    const float* p1w = (const float*)d_in[20];
    const float* p1b = (const float*)d_in[21];
    const float* p1g = (const float*)d_in[22];
    const float* p1bt = (const float*)d_in[23];
    const float* p2w = (const float*)d_in[24];
    const float* p2b = (const float*)d_in[25];
    const float* p2g = (const float*)d_in[26];
    const float* p2bt = (const float*)d_in[27];
    const float* p3w = (const float*)d_in[28];
    const float* p3b = (const float*)d_in[29];

    int Nn = in_sizes[0] / 4;
    int E  = in_sizes[1] / 3;
    const int* srcp = edge_idx;
    const int* dstp = edge_idx + E;
    float* outp = (float*)d_out;

    void *px_, *pe_, *pxl_, *pxr_, *plog_, *pumax_, *pden_, *phm_;
    cudaGetSymbolAddress(&px_, g_x);
    cudaGetSymbolAddress(&pe_, g_eemb);
    cudaGetSymbolAddress(&pxl_, g_xl);
    cudaGetSymbolAddress(&pxr_, g_xr);
    cudaGetSymbolAddress(&plog_, g_logits);
    cudaGetSymbolAddress(&pumax_, g_umax);
    cudaGetSymbolAddress(&pden_, g_den);
    cudaGetSymbolAddress(&phm_, g_hmean);
    float* px = (float*)px_;   float* pe = (float*)pe_;
    float* pxl = (float*)pxl_; float* pxr = (float*)pxr_;
    float* plog = (float*)plog_;
    unsigned* pumax = (unsigned*)pumax_;
    float* pden = (float*)pden_; float* phm = (float*)phm_;

    cudaFuncSetAttribute(edge_tf32_kernel,
                         cudaFuncAttributeMaxDynamicSharedMemorySize, TF_SMEM);
    cudaFuncSetAttribute(predictor_kernel,
                         cudaFuncAttributeMaxDynamicSharedMemorySize, PRED_SMEM);

    encoder_kernel<<<(Nn + 7) / 8, 256>>>(x, 4, ne_w, ne_b, ne_g, ne_bt, px, Nn);
    encoder_kernel<<<(E + 7) / 8, 256>>>(edge_attr, 3, ee_w, ee_b, ee_g, ee_bt, pe, E);

    dim3 gN((Nn + BM - 1) / BM, HC / BN);
    dim3 gEt((E + 127) / 128, HC / 64);

    for (int l = 0; l < 3; l++) {
        const float* Wl_l = Wl + (size_t)l * 96 * HC;
        const float* Wr_l = Wr + (size_t)l * 96 * HC;
        const float* We_l = We + (size_t)l * 96 * HC;
        gemm96_kernel<<<gN, 256>>>(px, Wl_l, bl + l * HC, pxl, Nn);
        gemm96_kernel<<<gN, 256>>>(px, Wr_l, br + l * HC, pxr, Nn);

        cudaMemsetAsync(plog, 0, (size_t)E * NH * sizeof(float), 0);
        cudaMemsetAsync(pumax, 0, (size_t)Nn * NH * sizeof(unsigned), 0);
        cudaMemsetAsync(pden, 0, (size_t)Nn * NH * sizeof(float), 0);
        cudaMemsetAsync(phm, 0, (size_t)Nn * HID * sizeof(float), 0);

        edge_tf32_kernel<<<gEt, 256, TF_SMEM>>>(pe, We_l, E, srcp, dstp,
                                                pxl, pxr, attw + l * NH * 96, plog);

        segmax_kernel<<<(E * NH + 255) / 256, 256>>>(dstp, plog, pumax, E);
        expsum_kernel<<<(E * NH + 255) / 256, 256>>>(dstp, plog, pumax, pden, E);
        agg_kernel<<<(E + 7) / 8, 256>>>(srcp, dstp, plog, pden, pxl, phm, E);
        nodeupd_kernel<<<(Nn + 7) / 8, 256>>>(cbias + l * HID, lng + l * HID,
                                              lnb + l * HID, (l < 2) ? 1 : 0, phm, px, Nn);
    }

    predictor_kernel<<<(E + 31) / 32, 256, PRED_SMEM>>>(
        srcp, dstp, px, pe,
        p1w, p1b, p1g, p1bt, p2w, p2b, p2g, p2bt, p3w, p3b, outp, E);
}

// round 6
// speedup vs baseline: 1.7955x; 1.1882x over previous
#include <cuda_runtime.h>
#include <math.h>

#define HID 96
#define HC  576
#define NH  6

typedef unsigned long long ull;

// ---------------- f32x2 packed helpers ----------------
__device__ __forceinline__ ull fma2(ull a, ull b, ull c) {
    ull d;
    asm("fma.rn.f32x2 %0, %1, %2, %3;" : "=l"(d) : "l"(a), "l"(b), "l"(c));
    return d;
}
__device__ __forceinline__ ull pack2(float x, float y) {
    ull r;
    asm("mov.b64 %0, {%1, %2};" : "=l"(r) : "f"(x), "f"(y));
    return r;
}
__device__ __forceinline__ ull dup2(float x) { return pack2(x, x); }
__device__ __forceinline__ float2 unpack2(ull v) {
    float2 r;
    asm("mov.b64 {%0, %1}, %2;" : "=f"(r.x), "=f"(r.y) : "l"(v));
    return r;
}
__device__ __forceinline__ unsigned f2tf32(float f) {
    unsigned r;
    asm("cvt.rna.tf32.f32 %0, %1;" : "=r"(r) : "f"(f));
    return r;
}
__device__ __forceinline__ void mma_tf32(float c[4],
    unsigned a0, unsigned a1, unsigned a2, unsigned a3,
    unsigned b0, unsigned b1)
{
    asm("mma.sync.aligned.m16n8k8.row.col.f32.tf32.tf32.f32 "
        "{%0,%1,%2,%3},{%4,%5,%6,%7},{%8,%9},{%0,%1,%2,%3};"
        : "+f"(c[0]), "+f"(c[1]), "+f"(c[2]), "+f"(c[3])
        : "r"(a0), "r"(a1), "r"(a2), "r"(a3), "r"(b0), "r"(b1));
}

// ---------------- scratch ----------------
__device__ float    g_x[20000 * HID];
__device__ float    g_eemb[200000 * HID];
__device__ float    g_xl[20000 * HC];
__device__ float    g_xr[20000 * HC];
__device__ float    g_logits[200000 * NH];
__device__ unsigned g_umax[20000 * NH];
__device__ float    g_den[20000 * NH];
__device__ float    g_hmean[20000 * HID];

__device__ __forceinline__ float warpsum32(float v) {
#pragma unroll
    for (int m = 16; m; m >>= 1) v += __shfl_xor_sync(0xffffffffu, v, m);
    return v;
}

// ---------------- encoder ----------------
__global__ void encoder_kernel(const float* __restrict__ in, int Fin,
                               const float* __restrict__ W, const float* __restrict__ b,
                               const float* __restrict__ g, const float* __restrict__ beta,
                               float* __restrict__ out, int M)
{
    int w    = (blockIdx.x * blockDim.x + threadIdx.x) >> 5;
    int lane = threadIdx.x & 31;
    if (w >= M) return;
    float xin[4];
#pragma unroll
    for (int k = 0; k < 4; k++) xin[k] = (k < Fin) ? in[(size_t)w * Fin + k] : 0.f;
    float v[3];
#pragma unroll
    for (int j = 0; j < 3; j++) {
        int c = lane + 32 * j;
        float acc = b[c];
        for (int k = 0; k < Fin; k++) acc = fmaf(xin[k], W[k * HID + c], acc);
        v[j] = acc;
    }
    float mu = warpsum32(v[0] + v[1] + v[2]) * (1.f / 96.f);
    float q = 0.f;
#pragma unroll
    for (int j = 0; j < 3; j++) { float d = v[j] - mu; q = fmaf(d, d, q); }
    float rstd = rsqrtf(warpsum32(q) * (1.f / 96.f) + 1e-5f);
#pragma unroll
    for (int j = 0; j < 3; j++) {
        int c = lane + 32 * j;
        float y = (v[j] - mu) * rstd * g[c] + beta[c];
        out[(size_t)w * HID + c] = fmaxf(y, 0.f);
    }
}

// ---------------- tf32 GEMM: C[M,576] = A[M,96] @ B[96,576] ----------------
// tile 128x64, 8 warps (4m x 2n), m16n8k8 tf32 mma, K=96 staged once.
// FUSED=false: store C + bias.  FUSED=true: fused GATv2 logit partials.
#define PAD_A 136
#define PAD_B 72
#define TF_SMEM ((96 * PAD_A + 96 * PAD_B) * 4)

template<bool FUSED>
__global__ __launch_bounds__(256) void tf32_gemm_kernel(
    const float* __restrict__ Ag, const float* __restrict__ Bg,
    const float* __restrict__ bias, float* __restrict__ C, int M,
    const int* __restrict__ src, const int* __restrict__ dst,
    const float* __restrict__ xl, const float* __restrict__ xr,
    const float* __restrict__ attw, float* __restrict__ logits)
{
    extern __shared__ unsigned sh_u[];
    unsigned* As = sh_u;                 // [96][PAD_A]  k-major (transposed)
    unsigned* Bs = sh_u + 96 * PAD_A;    // [96][PAD_B]

    int tid = threadIdx.x;
    int m0 = blockIdx.x * 128, n0 = blockIdx.y * 64;

    // stage A: convert to tf32 + transpose
    {
        int row   = tid >> 1;
        int kbase = (tid & 1) * 48;
        int m     = m0 + row;
#pragma unroll
        for (int i = 0; i < 12; i++) {
            float4 v = make_float4(0.f, 0.f, 0.f, 0.f);
            if (m < M) v = *(const float4*)(Ag + (size_t)m * 96 + kbase + i * 4);
            int k = kbase + i * 4;
            As[(k + 0) * PAD_A + row] = f2tf32(v.x);
            As[(k + 1) * PAD_A + row] = f2tf32(v.y);
            As[(k + 2) * PAD_A + row] = f2tf32(v.z);
            As[(k + 3) * PAD_A + row] = f2tf32(v.w);
        }
    }
    // stage B: convert to tf32
#pragma unroll
    for (int i = 0; i < 6; i++) {
        int lin = tid + 256 * i;
        int kr = lin >> 4, nq = (lin & 15) * 4;
        float4 v = *(const float4*)(Bg + (size_t)kr * HC + n0 + nq);
        uint4 o = make_uint4(f2tf32(v.x), f2tf32(v.y), f2tf32(v.z), f2tf32(v.w));
        *(uint4*)(Bs + kr * PAD_B + nq) = o;
    }
    __syncthreads();

    int wid = tid >> 5, lane = tid & 31;
    int wm = wid & 3, wn = wid >> 2;
    int g = lane >> 2, tig = lane & 3;
    int rowb = wm * 32;
    int colb = wn * 32;

    float acc[2][4][4];
#pragma unroll
    for (int mt = 0; mt < 2; mt++)
#pragma unroll
        for (int nt = 0; nt < 4; nt++)
#pragma unroll
            for (int q = 0; q < 4; q++) acc[mt][nt][q] = 0.f;

#pragma unroll
    for (int ks = 0; ks < 12; ks++) {
        int k0 = ks * 8;
        unsigned a[2][4];
#pragma unroll
        for (int mt = 0; mt < 2; mt++) {
            int rb = rowb + mt * 16 + g;
            a[mt][0] = As[(k0 + tig) * PAD_A + rb];
            a[mt][1] = As[(k0 + tig) * PAD_A + rb + 8];
            a[mt][2] = As[(k0 + tig + 4) * PAD_A + rb];
            a[mt][3] = As[(k0 + tig + 4) * PAD_A + rb + 8];
        }
        unsigned bf[4][2];
#pragma unroll
        for (int nt = 0; nt < 4; nt++) {
            int cb = colb + nt * 8 + g;
            bf[nt][0] = Bs[(k0 + tig) * PAD_B + cb];
            bf[nt][1] = Bs[(k0 + tig + 4) * PAD_B + cb];
        }
#pragma unroll
        for (int mt = 0; mt < 2; mt++)
#pragma unroll
            for (int nt = 0; nt < 4; nt++)
                mma_tf32(acc[mt][nt], a[mt][0], a[mt][1], a[mt][2], a[mt][3],
                         bf[nt][0], bf[nt][1]);
    }

    if (!FUSED) {
        // store with bias: fragment rows g / g+8, cols 2*tig .. +1
#pragma unroll
        for (int nt = 0; nt < 4; nt++) {
            int c = n0 + colb + nt * 8 + 2 * tig;
            float2 bq = *(const float2*)(bias + c);
#pragma unroll
            for (int mt = 0; mt < 2; mt++) {
                int r0 = m0 + rowb + mt * 16 + g;
                if (r0 < M) {
                    float2 o = make_float2(acc[mt][nt][0] + bq.x, acc[mt][nt][1] + bq.y);
                    *(float2*)(C + (size_t)r0 * HC + c) = o;
                }
                int r1 = r0 + 8;
                if (r1 < M) {
                    float2 o = make_float2(acc[mt][nt][2] + bq.x, acc[mt][nt][3] + bq.y);
                    *(float2*)(C + (size_t)r1 * HC + c) = o;
                }
            }
        }
    } else {
        int h = (n0 + colb) / 96;      // warp's 32 cols stay in one head
#pragma unroll
        for (int mt = 0; mt < 2; mt++) {
#pragma unroll
            for (int half = 0; half < 2; half++) {
                int m = m0 + rowb + mt * 16 + half * 8 + g;
                float partial = 0.f;
                if (m < M) {
                    int s = src[m], d = dst[m];
                    const float* xls = xl + (size_t)s * HC;
                    const float* xrd = xr + (size_t)d * HC;
#pragma unroll
                    for (int nt = 0; nt < 4; nt++) {
                        int c = n0 + colb + nt * 8 + 2 * tig;
                        float2 xlv = *(const float2*)(xls + c);
                        float2 xrv = *(const float2*)(xrd + c);
                        float aw0 = attw[c], aw1 = attw[c + 1];
                        float a0 = acc[mt][nt][half * 2 + 0];
                        float a1 = acc[mt][nt][half * 2 + 1];
                        float t0 = a0 + xlv.x + xrv.x; t0 = (t0 > 0.f) ? t0 : 0.2f * t0;
                        float t1 = a1 + xlv.y + xrv.y; t1 = (t1 > 0.f) ? t1 : 0.2f * t1;
                        partial = fmaf(t0, aw0, fmaf(t1, aw1, partial));
                    }
                }
                partial += __shfl_down_sync(0xffffffffu, partial, 1, 4);
                partial += __shfl_down_sync(0xffffffffu, partial, 2, 4);
                if (tig == 0 && m < M)
                    atomicAdd(&logits[(size_t)m * NH + h], partial);
            }
        }
    }
}

// ---------------- segment max ----------------
__global__ void segmax_kernel(const int* __restrict__ dst, const float* __restrict__ logits,
                              unsigned* __restrict__ umax, int E)
{
    int t = blockIdx.x * blockDim.x + threadIdx.x;
    if (t >= E * NH) return;
    int e = t / NH, h = t - e * NH;
    float p = logits[t];
    unsigned u = __float_as_uint(p);
    u ^= (u >> 31) ? 0xFFFFFFFFu : 0x80000000u;
    atomicMax(&umax[dst[e] * NH + h], u);
}

// ---------------- exp + denominator ----------------
__global__ void expsum_kernel(const int* __restrict__ dst, float* __restrict__ logits,
                              const unsigned* __restrict__ umax, float* __restrict__ den, int E)
{
    int t = blockIdx.x * blockDim.x + threadIdx.x;
    if (t >= E * NH) return;
    int e = t / NH, h = t - e * NH;
    int d = dst[e];
    unsigned u = umax[d * NH + h];
    float m = (u & 0x80000000u) ? __uint_as_float(u ^ 0x80000000u) : __uint_as_float(~u);
    float ex = expf(logits[t] - m);
    logits[t] = ex;
    atomicAdd(&den[d * NH + h], ex);
}

// ---------------- aggregate ----------------
__global__ void agg_kernel(const int* __restrict__ src, const int* __restrict__ dst,
                           const float* __restrict__ ex, const float* __restrict__ den,
                           const float* __restrict__ xl, float* __restrict__ hmean, int E)
{
    int e    = (blockIdx.x * blockDim.x + threadIdx.x) >> 5;
    int lane = threadIdx.x & 31;
    if (e >= E) return;
    int s = src[e], d = dst[e];
    float a = 0.f;
    if (lane < NH) a = ex[e * NH + lane] / (den[d * NH + lane] + 1e-16f);
    float alpha[NH];
#pragma unroll
    for (int h = 0; h < NH; h++) alpha[h] = __shfl_sync(0xffffffffu, a, h);
    const float* xls = xl + (size_t)s * HC;
#pragma unroll
    for (int j = 0; j < 3; j++) {
        int c = lane + 32 * j;
        float v = 0.f;
#pragma unroll
        for (int h = 0; h < NH; h++) v = fmaf(alpha[h], xls[h * 96 + c], v);
        atomicAdd(&hmean[(size_t)d * HID + c], v * (1.f / 6.f));
    }
}

// ---------------- node update ----------------
__global__ void nodeupd_kernel(const float* __restrict__ cb, const float* __restrict__ g,
                               const float* __restrict__ bt, int doElu,
                               const float* __restrict__ hmean, float* __restrict__ x, int M)
{
    int n    = (blockIdx.x * blockDim.x + threadIdx.x) >> 5;
    int lane = threadIdx.x & 31;
    if (n >= M) return;
    float v[3];
#pragma unroll
    for (int j = 0; j < 3; j++) {
        int c = lane + 32 * j;
        float hv = hmean[(size_t)n * HID + c] + cb[c];
        if (doElu) hv = (hv > 0.f) ? hv : (expf(hv) - 1.f);
        v[j] = hv;
    }
    float mu = warpsum32(v[0] + v[1] + v[2]) * (1.f / 96.f);
    float q = 0.f;
#pragma unroll
    for (int j = 0; j < 3; j++) { float d = v[j] - mu; q = fmaf(d, d, q); }
    float rstd = rsqrtf(warpsum32(q) * (1.f / 96.f) + 1e-5f);
#pragma unroll
    for (int j = 0; j < 3; j++) {
        int c = lane + 32 * j;
        float y = (v[j] - mu) * rstd * g[c] + bt[c];
        x[(size_t)n * HID + c] += y;
    }
}

// ---------------- persistent fused predictor MLP ----------------
// 148 blocks x 256 threads; batches of 64 edges; edges packed in PAIRS into
// f32x2 lanes. smem: p1w (144KB) + consts + packed ctx (72KB) ~ 219KB.
// p2w read from global (L2-resident, 32KB).
#define PF_P1W 36864
#define PF_P3W 64
#define PF_C1  384
#define PF_C2  192
#define PF_CTX_U64 (32 * 288)     // 32 pairs x 288 ull
#define PRED_SMEM ((PF_P1W + PF_P3W + PF_C1 + PF_C2) * 4 + PF_CTX_U64 * 8)

__global__ __launch_bounds__(256) void predictor_kernel(
    const int* __restrict__ src, const int* __restrict__ dst,
    const float* __restrict__ xnode, const float* __restrict__ eemb,
    const float* __restrict__ p1w, const float* __restrict__ p1b,
    const float* __restrict__ p1g, const float* __restrict__ p1bt,
    const float* __restrict__ p2w, const float* __restrict__ p2b,
    const float* __restrict__ p2g, const float* __restrict__ p2bt,
    const float* __restrict__ p3w, const float* __restrict__ p3b,
    float* __restrict__ out, int E)
{
    extern __shared__ float sm[];
    float* s_p1w = sm;                       // [288][128]
    float* s_p3w = s_p1w + PF_P1W;           // [64]
    float* s_c1  = s_p3w + PF_P3W;           // p1b|p1g|p1bt
    float* s_c2  = s_c1 + PF_C1;             // p2b|p2g|p2bt
    ull*   s_ctx = (ull*)(s_c2 + PF_C2);     // [32 pairs][288] packed (even,odd)

    int tid = threadIdx.x;
    // stage weights once
    for (int i = tid; i < PF_P1W / 4; i += 256) ((float4*)s_p1w)[i] = ((const float4*)p1w)[i];
    if (tid < 64) s_p3w[tid] = p3w[tid];
    if (tid < 128) { s_c1[tid] = p1b[tid]; s_c1[128 + tid] = p1g[tid]; s_c1[256 + tid] = p1bt[tid]; }
    if (tid < 64)  { s_c2[tid] = p2b[tid]; s_c2[64 + tid] = p2g[tid]; s_c2[128 + tid] = p2bt[tid]; }
    float pb = p3b[0];

    int w = tid >> 5, lane = tid & 31;
    int j1 = lane * 4;                        // layer1 outputs
    int j2 = lane * 2;                        // layer2 outputs
    int NB = (E + 63) / 64;

    for (int bb = blockIdx.x; bb < NB; bb += gridDim.x) {
        __syncthreads();                      // previous batch fully consumed
        // stage ctx: 64 edges x 288, via float4 chunks, packed into pairs
        for (int i = tid; i < 64 * 72; i += 256) {
            int el = i / 72, kq = (i - el * 72) * 4;
            int e = bb * 64 + el; if (e > E - 1) e = E - 1;
            float4 v;
            if (kq < 96)       v = *(const float4*)(xnode + (size_t)src[e] * HID + kq);
            else if (kq < 192) v = *(const float4*)(xnode + (size_t)dst[e] * HID + (kq - 96));
            else               v = *(const float4*)(eemb + (size_t)e * HID + (kq - 192));
            float* base = (float*)(s_ctx + (size_t)(el >> 1) * 288 + kq);
            int hoff = el & 1;
            base[0 + hoff] = v.x; base[2 + hoff] = v.y;
            base[4 + hoff] = v.z; base[6 + hoff] = v.w;
        }
        __syncthreads();

        // warp handles pairs 4w..4w+3 (edges 8w..8w+7), outputs j1..j1+3
        const ull* cp0 = s_ctx + (size_t)(4 * w + 0) * 288;
        const ull* cp1 = s_ctx + (size_t)(4 * w + 1) * 288;
        const ull* cp2 = s_ctx + (size_t)(4 * w + 2) * 288;
        const ull* cp3 = s_ctx + (size_t)(4 * w + 3) * 288;

        ull acc1[4][4];
#pragma unroll
        for (int q = 0; q < 4; q++)
#pragma unroll
            for (int j = 0; j < 4; j++) acc1[q][j] = 0ull;

#pragma unroll 4
        for (int k = 0; k < 288; k++) {
            ull c0 = cp0[k], c1 = cp1[k], c2 = cp2[k], c3 = cp3[k];
            float4 wv = *(const float4*)(s_p1w + k * 128 + j1);
            ull w0 = dup2(wv.x), w1 = dup2(wv.y), w2 = dup2(wv.z), w3 = dup2(wv.w);
            acc1[0][0] = fma2(c0, w0, acc1[0][0]); acc1[0][1] = fma2(c0, w1, acc1[0][1]);
            acc1[0][2] = fma2(c0, w2, acc1[0][2]); acc1[0][3] = fma2(c0, w3, acc1[0][3]);
            acc1[1][0] = fma2(c1, w0, acc1[1][0]); acc1[1][1] = fma2(c1, w1, acc1[1][1]);
            acc1[1][2] = fma2(c1, w2, acc1[1][2]); acc1[1][3] = fma2(c1, w3, acc1[1][3]);
            acc1[2][0] = fma2(c2, w0, acc1[2][0]); acc1[2][1] = fma2(c2, w1, acc1[2][1]);
            acc1[2][2] = fma2(c2, w2, acc1[2][2]); acc1[2][3] = fma2(c2, w3, acc1[2][3]);
            acc1[3][0] = fma2(c3, w0, acc1[3][0]); acc1[3][1] = fma2(c3, w1, acc1[3][1]);
            acc1[3][2] = fma2(c3, w2, acc1[3][2]); acc1[3][3] = fma2(c3, w3, acc1[3][3]);
        }

        float hE[4][4], hO[4][4];
#pragma unroll
        for (int q = 0; q < 4; q++)
#pragma unroll
            for (int j = 0; j < 4; j++) {
                float2 u = unpack2(acc1[q][j]);
                hE[q][j] = u.x + s_c1[j1 + j];
                hO[q][j] = u.y + s_c1[j1 + j];
            }
        // LN over 128 per edge (warp-wide)
#pragma unroll
        for (int q = 0; q < 4; q++) {
            float sE = hE[q][0] + hE[q][1] + hE[q][2] + hE[q][3];
            float sO = hO[q][0] + hO[q][1] + hO[q][2] + hO[q][3];
            float muE = warpsum32(sE) * (1.f / 128.f);
            float muO = warpsum32(sO) * (1.f / 128.f);
            float qE = 0.f, qO = 0.f;
#pragma unroll
            for (int j = 0; j < 4; j++) {
                float d;
                d = hE[q][j] - muE; qE = fmaf(d, d, qE);
                d = hO[q][j] - muO; qO = fmaf(d, d, qO);
            }
            float rE = rsqrtf(warpsum32(qE) * (1.f / 128.f) + 1e-5f);
            float rO = rsqrtf(warpsum32(qO) * (1.f / 128.f) + 1e-5f);
#pragma unroll
            for (int j = 0; j < 4; j++) {
                float gma = s_c1[128 + j1 + j], bta = s_c1[256 + j1 + j];
                hE[q][j] = fmaxf((hE[q][j] - muE) * rE * gma + bta, 0.f);
                hO[q][j] = fmaxf((hO[q][j] - muO) * rO * gma + bta, 0.f);
            }
        }
        __syncwarp();
        // store packed h1 into own ctx rows (first 128 slots)
#pragma unroll
        for (int q = 0; q < 4; q++) {
            ull* hp = s_ctx + (size_t)(4 * w + q) * 288;
#pragma unroll
            for (int j = 0; j < 4; j++)
                hp[j1 + j] = pack2(hE[q][j], hO[q][j]);
        }
        __syncwarp();

        // layer 2: 64 outputs, p2w from global (L2-resident)
        ull acc2[4][2];
#pragma unroll
        for (int q = 0; q < 4; q++) { acc2[q][0] = 0ull; acc2[q][1] = 0ull; }
#pragma unroll 4
        for (int k = 0; k < 128; k++) {
            ull c0 = cp0[k], c1 = cp1[k], c2 = cp2[k], c3 = cp3[k];
            float2 wv = __ldg((const float2*)(p2w + k * 64 + j2));
            ull w0 = dup2(wv.x), w1 = dup2(wv.y);
            acc2[0][0] = fma2(c0, w0, acc2[0][0]); acc2[0][1] = fma2(c0, w1, acc2[0][1]);
            acc2[1][0] = fma2(c1, w0, acc2[1][0]); acc2[1][1] = fma2(c1, w1, acc2[1][1]);
            acc2[2][0] = fma2(c2, w0, acc2[2][0]); acc2[2][1] = fma2(c2, w1, acc2[2][1]);
            acc2[3][0] = fma2(c3, w0, acc2[3][0]); acc2[3][1] = fma2(c3, w1, acc2[3][1]);
        }

        float gEo[4][2], gOo[4][2];
#pragma unroll
        for (int q = 0; q < 4; q++)
#pragma unroll
            for (int j = 0; j < 2; j++) {
                float2 u = unpack2(acc2[q][j]);
                gEo[q][j] = u.x + s_c2[j2 + j];
                gOo[q][j] = u.y + s_c2[j2 + j];
            }
#pragma unroll
        for (int q = 0; q < 4; q++) {
            float sE = gEo[q][0] + gEo[q][1];
            float sO = gOo[q][0] + gOo[q][1];
            float muE = warpsum32(sE) * (1.f / 64.f);
            float muO = warpsum32(sO) * (1.f / 64.f);
            float qE = 0.f, qO = 0.f;
#pragma unroll
            for (int j = 0; j < 2; j++) {
                float d;
                d = gEo[q][j] - muE; qE = fmaf(d, d, qE);
                d = gOo[q][j] - muO; qO = fmaf(d, d, qO);
            }
            float rE = rsqrtf(warpsum32(qE) * (1.f / 64.f) + 1e-5f);
            float rO = rsqrtf(warpsum32(qO) * (1.f / 64.f) + 1e-5f);
            float oE = 0.f, oO = 0.f;
#pragma unroll
            for (int j = 0; j < 2; j++) {
                float gma = s_c2[64 + j2 + j], bta = s_c2[128 + j2 + j];
                float vE = fmaxf((gEo[q][j] - muE) * rE * gma + bta, 0.f);
                float vO = fmaxf((gOo[q][j] - muO) * rO * gma + bta, 0.f);
                float w3v = s_p3w[j2 + j];
                oE = fmaf(vE, w3v, oE);
                oO = fmaf(vO, w3v, oO);
            }
            oE = warpsum32(oE);
            oO = warpsum32(oO);
            if (lane == 0) {
                int e0 = bb * 64 + 8 * w + 2 * q;
                if (e0 < E) out[e0] = oE + pb;
                if (e0 + 1 < E) out[e0 + 1] = oO + pb;
            }
        }
    }
}

// ---------------- launch ----------------
extern "C" void kernel_launch(void* const* d_in, const int* in_sizes, int n_in,
                              void* d_out, int out_size)
{
    const float* x         = (const float*)d_in[0];
    const float* edge_attr = (const float*)d_in[1];
    const int*   edge_idx  = (const int*)d_in[2];
    const float* ne_w = (const float*)d_in[3];
    const float* ne_b = (const float*)d_in[4];
    const float* ne_g = (const float*)d_in[5];
    const float* ne_bt = (const float*)d_in[6];
    const float* ee_w = (const float*)d_in[7];
    const float* ee_b = (const float*)d_in[8];
    const float* ee_g = (const float*)d_in[9];
    const float* ee_bt = (const float*)d_in[10];
    const float* Wl = (const float*)d_in[11];
    const float* bl = (const float*)d_in[12];
    const float* Wr = (const float*)d_in[13];
    const float* br = (const float*)d_in[14];
    const float* We = (const float*)d_in[15];
    const float* attw = (const float*)d_in[16];
    const float* cbias = (const float*)d_in[17];
    const float* lng = (const float*)d_in[18];
    const float* lnb = (const float*)d_in[19];
    const float* p1w = (const float*)d_in[20];
    const float* p1b = (const float*)d_in[21];
    const float* p1g = (const float*)d_in[22];
    const float* p1bt = (const float*)d_in[23];
    const float* p2w = (const float*)d_in[24];
    const float* p2b = (const float*)d_in[25];
    const float* p2g = (const float*)d_in[26];
    const float* p2bt = (const float*)d_in[27];
    const float* p3w = (const float*)d_in[28];
    const float* p3b = (const float*)d_in[29];

    int Nn = in_sizes[0] / 4;
    int E  = in_sizes[1] / 3;
    const int* srcp = edge_idx;
    const int* dstp = edge_idx + E;
    float* outp = (float*)d_out;

    void *px_, *pe_, *pxl_, *pxr_, *plog_, *pumax_, *pden_, *phm_;
    cudaGetSymbolAddress(&px_, g_x);
    cudaGetSymbolAddress(&pe_, g_eemb);
    cudaGetSymbolAddress(&pxl_, g_xl);
    cudaGetSymbolAddress(&pxr_, g_xr);
    cudaGetSymbolAddress(&plog_, g_logits);
    cudaGetSymbolAddress(&pumax_, g_umax);
    cudaGetSymbolAddress(&pden_, g_den);
    cudaGetSymbolAddress(&phm_, g_hmean);
    float* px = (float*)px_;   float* pe = (float*)pe_;
    float* pxl = (float*)pxl_; float* pxr = (float*)pxr_;
    float* plog = (float*)plog_;
    unsigned* pumax = (unsigned*)pumax_;
    float* pden = (float*)pden_; float* phm = (float*)phm_;

    cudaFuncSetAttribute(tf32_gemm_kernel<false>,
                         cudaFuncAttributeMaxDynamicSharedMemorySize, TF_SMEM);
    cudaFuncSetAttribute(tf32_gemm_kernel<true>,
                         cudaFuncAttributeMaxDynamicSharedMemorySize, TF_SMEM);
    cudaFuncSetAttribute(predictor_kernel,
                         cudaFuncAttributeMaxDynamicSharedMemorySize, PRED_SMEM);

    encoder_kernel<<<(Nn + 7) / 8, 256>>>(x, 4, ne_w, ne_b, ne_g, ne_bt, px, Nn);
    encoder_kernel<<<(E + 7) / 8, 256>>>(edge_attr, 3, ee_w, ee_b, ee_g, ee_bt, pe, E);

    dim3 gNt((Nn + 127) / 128, HC / 64);
    dim3 gEt((E + 127) / 128, HC / 64);

    for (int l = 0; l < 3; l++) {
        const float* Wl_l = Wl + (size_t)l * 96 * HC;
        const float* Wr_l = Wr + (size_t)l * 96 * HC;
        const float* We_l = We + (size_t)l * 96 * HC;
        tf32_gemm_kernel<false><<<gNt, 256, TF_SMEM>>>(px, Wl_l, bl + l * HC, pxl, Nn,
                                                       0, 0, 0, 0, 0, 0);
        tf32_gemm_kernel<false><<<gNt, 256, TF_SMEM>>>(px, Wr_l, br + l * HC, pxr, Nn,
                                                       0, 0, 0, 0, 0, 0);

        cudaMemsetAsync(plog, 0, (size_t)E * NH * sizeof(float), 0);
        cudaMemsetAsync(pumax, 0, (size_t)Nn * NH * sizeof(unsigned), 0);
        cudaMemsetAsync(pden, 0, (size_t)Nn * NH * sizeof(float), 0);
        cudaMemsetAsync(phm, 0, (size_t)Nn * HID * sizeof(float), 0);

        tf32_gemm_kernel<true><<<gEt, 256, TF_SMEM>>>(pe, We_l, (const float*)0, (float*)0, E,
                                                      srcp, dstp, pxl, pxr,
                                                      attw + l * NH * 96, plog);

        segmax_kernel<<<(E * NH + 255) / 256, 256>>>(dstp, plog, pumax, E);
        expsum_kernel<<<(E * NH + 255) / 256, 256>>>(dstp, plog, pumax, pden, E);
        agg_kernel<<<(E + 7) / 8, 256>>>(srcp, dstp, plog, pden, pxl, phm, E);
        nodeupd_kernel<<<(Nn + 7) / 8, 256>>>(cbias + l * HID, lng + l * HID,
                                              lnb + l * HID, (l < 2) ? 1 : 0, phm, px, Nn);
    }

    predictor_kernel<<<148, 256, PRED_SMEM>>>(
        srcp, dstp, px, pe,
        p1w, p1b, p1g, p1bt, p2w, p2b, p2g, p2bt, p3w, p3b, outp, E);
}

// round 7
// speedup vs baseline: 1.8536x; 1.0324x over previous
#include <cuda_runtime.h>
#include <math.h>

#define HID 96
#define HC  576
#define NH  6

typedef unsigned long long ull;

// ---------------- f32x2 packed helpers ----------------
__device__ __forceinline__ ull fma2(ull a, ull b, ull c) {
    ull d;
    asm("fma.rn.f32x2 %0, %1, %2, %3;" : "=l"(d) : "l"(a), "l"(b), "l"(c));
    return d;
}
__device__ __forceinline__ ull pack2(float x, float y) {
    ull r;
    asm("mov.b64 %0, {%1, %2};" : "=l"(r) : "f"(x), "f"(y));
    return r;
}
__device__ __forceinline__ ull dup2(float x) { return pack2(x, x); }
__device__ __forceinline__ float2 unpack2(ull v) {
    float2 r;
    asm("mov.b64 {%0, %1}, %2;" : "=f"(r.x), "=f"(r.y) : "l"(v));
    return r;
}
__device__ __forceinline__ unsigned f2tf32(float f) {
    unsigned r;
    asm("cvt.rna.tf32.f32 %0, %1;" : "=r"(r) : "f"(f));
    return r;
}
__device__ __forceinline__ ull pack_tf32(float a, float b) {
    unsigned lo = f2tf32(a), hi = f2tf32(b);
    ull r;
    asm("mov.b64 %0, {%1, %2};" : "=l"(r) : "r"(lo), "r"(hi));
    return r;
}
__device__ __forceinline__ void mma_tf32(float c[4],
    unsigned a0, unsigned a1, unsigned a2, unsigned a3,
    unsigned b0, unsigned b1)
{
    asm("mma.sync.aligned.m16n8k8.row.col.f32.tf32.tf32.f32 "
        "{%0,%1,%2,%3},{%4,%5,%6,%7},{%8,%9},{%0,%1,%2,%3};"
        : "+f"(c[0]), "+f"(c[1]), "+f"(c[2]), "+f"(c[3])
        : "r"(a0), "r"(a1), "r"(a2), "r"(a3), "r"(b0), "r"(b1));
}

// ---------------- scratch ----------------
__device__ float    g_x[20000 * HID];
__device__ float    g_eemb[200000 * HID];
__device__ float    g_xl[20000 * HC];
__device__ float    g_xr[20000 * HC];
__device__ float    g_logits[200000 * NH];
__device__ unsigned g_umax[20000 * NH];
__device__ float    g_den[20000 * NH];
__device__ float    g_hmean[20000 * HID];

__device__ __forceinline__ float warpsum32(float v) {
#pragma unroll
    for (int m = 16; m; m >>= 1) v += __shfl_xor_sync(0xffffffffu, v, m);
    return v;
}

// ---------------- encoder ----------------
__global__ void encoder_kernel(const float* __restrict__ in, int Fin,
                               const float* __restrict__ W, const float* __restrict__ b,
                               const float* __restrict__ g, const float* __restrict__ beta,
                               float* __restrict__ out, int M)
{
    int w    = (blockIdx.x * blockDim.x + threadIdx.x) >> 5;
    int lane = threadIdx.x & 31;
    if (w >= M) return;
    float xin[4];
#pragma unroll
    for (int k = 0; k < 4; k++) xin[k] = (k < Fin) ? in[(size_t)w * Fin + k] : 0.f;
    float v[3];
#pragma unroll
    for (int j = 0; j < 3; j++) {
        int c = lane + 32 * j;
        float acc = b[c];
        for (int k = 0; k < Fin; k++) acc = fmaf(xin[k], W[k * HID + c], acc);
        v[j] = acc;
    }
    float mu = warpsum32(v[0] + v[1] + v[2]) * (1.f / 96.f);
    float q = 0.f;
#pragma unroll
    for (int j = 0; j < 3; j++) { float d = v[j] - mu; q = fmaf(d, d, q); }
    float rstd = rsqrtf(warpsum32(q) * (1.f / 96.f) + 1e-5f);
#pragma unroll
    for (int j = 0; j < 3; j++) {
        int c = lane + 32 * j;
        float y = (v[j] - mu) * rstd * g[c] + beta[c];
        out[(size_t)w * HID + c] = fmaxf(y, 0.f);
    }
}

// ---------------- tf32 GEMM: C[M,576] = A[M,96] @ B[96,576] ----------------
// tile 128x96 (one head per block), 12 warps (4m x 3n), m16n8k8 tf32 mma.
// Packed-pair smem: A[ks][row][tig] and B[ks][col][tig] as ull (k_tig, k_tig+4)
// -> conflict-free LDS.64 fragment loads, 8 LDS + 8 mma per k-step per warp.
#define AU_ULL (12 * 512)          // 12 ks x 128 rows x 4 tig
#define BU_ULL (12 * 384)          // 12 ks x 96 cols x 4 tig
#define TF_SMEM ((AU_ULL + BU_ULL) * 8)

template<bool FUSED>
__global__ __launch_bounds__(384) void tf32_gemm_kernel(
    const float* __restrict__ Ag, const float* __restrict__ Bg,
    const float* __restrict__ bias, float* __restrict__ C, int M,
    const int* __restrict__ src, const int* __restrict__ dst,
    const float* __restrict__ xl, const float* __restrict__ xr,
    const float* __restrict__ attw, float* __restrict__ logits)
{
    extern __shared__ ull sh64[];
    ull* Au = sh64;                // [ks*512 + row*4 + tig]
    ull* Bu = sh64 + AU_ULL;       // [ks*384 + col*4 + tig]

    int tid = threadIdx.x;
    int m0 = blockIdx.x * 128, n0 = blockIdx.y * 96;

    // ---- stage A: pack (k_tig, k_tig+4) tf32 pairs ----
    {
        int row = tid & 127;
        int kg  = tid >> 7;            // 0..2
        int m = m0 + row;
        const float* arow = Ag + (size_t)m * 96;
#pragma unroll
        for (int i = 0; i < 4; i++) {
            int ks = kg * 4 + i;
            float4 lo = make_float4(0.f, 0.f, 0.f, 0.f);
            float4 hi = make_float4(0.f, 0.f, 0.f, 0.f);
            if (m < M) {
                lo = *(const float4*)(arow + ks * 8);
                hi = *(const float4*)(arow + ks * 8 + 4);
            }
            ull p0 = pack_tf32(lo.x, hi.x);
            ull p1 = pack_tf32(lo.y, hi.y);
            ull p2 = pack_tf32(lo.z, hi.z);
            ull p3 = pack_tf32(lo.w, hi.w);
            ull* dstp = Au + ks * 512 + row * 4;
            *(ulonglong2*)(dstp)     = make_ulonglong2(p0, p1);
            *(ulonglong2*)(dstp + 2) = make_ulonglong2(p2, p3);
        }
    }
    // ---- stage B ----
    for (int t = tid; t < 1152; t += 384) {
        int ks  = t / 96;
        int rem = t - ks * 96;
        int q = rem >> 2;              // col quad 0..23
        int r = rem & 3;               // tig
        int krow = ks * 8 + r;
        const float* b0 = Bg + (size_t)krow * HC + n0 + q * 4;
        float4 lo = *(const float4*)b0;
        float4 hi = *(const float4*)(b0 + 4 * HC);
        ull* dstb = Bu + ks * 384 + (q * 4) * 4 + r;
        dstb[0]  = pack_tf32(lo.x, hi.x);
        dstb[4]  = pack_tf32(lo.y, hi.y);
        dstb[8]  = pack_tf32(lo.z, hi.z);
        dstb[12] = pack_tf32(lo.w, hi.w);
    }
    __syncthreads();

    int wid = tid >> 5, lane = tid & 31;
    int wm = wid & 3, wn = wid >> 2;   // 4m x 3n
    int g = lane >> 2, tig = lane & 3;
    int rowb = wm * 32;
    int colb = wn * 32;

    float acc[2][4][4];
#pragma unroll
    for (int mt = 0; mt < 2; mt++)
#pragma unroll
        for (int nt = 0; nt < 4; nt++)
#pragma unroll
            for (int q = 0; q < 4; q++) acc[mt][nt][q] = 0.f;

#pragma unroll
    for (int ks = 0; ks < 12; ks++) {
        const ull* Ak = Au + ks * 512;
        const ull* Bk = Bu + ks * 384;
        uint2 pa[2][2];
#pragma unroll
        for (int mt = 0; mt < 2; mt++) {
            int rb = rowb + mt * 16 + g;
            pa[mt][0] = *(const uint2*)(Ak + rb * 4 + tig);
            pa[mt][1] = *(const uint2*)(Ak + (rb + 8) * 4 + tig);
        }
#pragma unroll
        for (int nt = 0; nt < 4; nt++) {
            int cb = colb + nt * 8 + g;
            uint2 pb = *(const uint2*)(Bk + cb * 4 + tig);
#pragma unroll
            for (int mt = 0; mt < 2; mt++)
                mma_tf32(acc[mt][nt],
                         pa[mt][0].x, pa[mt][1].x, pa[mt][0].y, pa[mt][1].y,
                         pb.x, pb.y);
        }
    }

    if (!FUSED) {
#pragma unroll
        for (int nt = 0; nt < 4; nt++) {
            int c = n0 + colb + nt * 8 + 2 * tig;
            float2 bq = *(const float2*)(bias + c);
#pragma unroll
            for (int mt = 0; mt < 2; mt++) {
                int r0 = m0 + rowb + mt * 16 + g;
                if (r0 < M) {
                    float2 o = make_float2(acc[mt][nt][0] + bq.x, acc[mt][nt][1] + bq.y);
                    *(float2*)(C + (size_t)r0 * HC + c) = o;
                }
                int r1 = r0 + 8;
                if (r1 < M) {
                    float2 o = make_float2(acc[mt][nt][2] + bq.x, acc[mt][nt][3] + bq.y);
                    *(float2*)(C + (size_t)r1 * HC + c) = o;
                }
            }
        }
    } else {
        int h = blockIdx.y;            // one head per block (n0 = h*96)
#pragma unroll
        for (int mt = 0; mt < 2; mt++) {
#pragma unroll
            for (int half = 0; half < 2; half++) {
                int m = m0 + rowb + mt * 16 + half * 8 + g;
                float partial = 0.f;
                if (m < M) {
                    int s = src[m], d = dst[m];
                    const float* xls = xl + (size_t)s * HC;
                    const float* xrd = xr + (size_t)d * HC;
#pragma unroll
                    for (int nt = 0; nt < 4; nt++) {
                        int c = n0 + colb + nt * 8 + 2 * tig;
                        float2 xlv = *(const float2*)(xls + c);
                        float2 xrv = *(const float2*)(xrd + c);
                        float aw0 = attw[c], aw1 = attw[c + 1];
                        float a0 = acc[mt][nt][half * 2 + 0];
                        float a1 = acc[mt][nt][half * 2 + 1];
                        float t0 = a0 + xlv.x + xrv.x; t0 = (t0 > 0.f) ? t0 : 0.2f * t0;
                        float t1 = a1 + xlv.y + xrv.y; t1 = (t1 > 0.f) ? t1 : 0.2f * t1;
                        partial = fmaf(t0, aw0, fmaf(t1, aw1, partial));
                    }
                }
                partial += __shfl_down_sync(0xffffffffu, partial, 1, 4);
                partial += __shfl_down_sync(0xffffffffu, partial, 2, 4);
                if (tig == 0 && m < M)
                    atomicAdd(&logits[(size_t)m * NH + h], partial);
            }
        }
    }
}

// ---------------- segment max ----------------
__global__ void segmax_kernel(const int* __restrict__ dst, const float* __restrict__ logits,
                              unsigned* __restrict__ umax, int E)
{
    int t = blockIdx.x * blockDim.x + threadIdx.x;
    if (t >= E * NH) return;
    int e = t / NH, h = t - e * NH;
    float p = logits[t];
    unsigned u = __float_as_uint(p);
    u ^= (u >> 31) ? 0xFFFFFFFFu : 0x80000000u;
    atomicMax(&umax[dst[e] * NH + h], u);
}

// ---------------- exp + denominator ----------------
__global__ void expsum_kernel(const int* __restrict__ dst, float* __restrict__ logits,
                              const unsigned* __restrict__ umax, float* __restrict__ den, int E)
{
    int t = blockIdx.x * blockDim.x + threadIdx.x;
    if (t >= E * NH) return;
    int e = t / NH, h = t - e * NH;
    int d = dst[e];
    unsigned u = umax[d * NH + h];
    float m = (u & 0x80000000u) ? __uint_as_float(u ^ 0x80000000u) : __uint_as_float(~u);
    float ex = expf(logits[t] - m);
    logits[t] = ex;
    atomicAdd(&den[d * NH + h], ex);
}

// ---------------- aggregate ----------------
__global__ void agg_kernel(const int* __restrict__ src, const int* __restrict__ dst,
                           const float* __restrict__ ex, const float* __restrict__ den,
                           const float* __restrict__ xl, float* __restrict__ hmean, int E)
{
    int e    = (blockIdx.x * blockDim.x + threadIdx.x) >> 5;
    int lane = threadIdx.x & 31;
    if (e >= E) return;
    int s = src[e], d = dst[e];
    float a = 0.f;
    if (lane < NH) a = ex[e * NH + lane] / (den[d * NH + lane] + 1e-16f);
    float alpha[NH];
#pragma unroll
    for (int h = 0; h < NH; h++) alpha[h] = __shfl_sync(0xffffffffu, a, h);
    const float* xls = xl + (size_t)s * HC;
#pragma unroll
    for (int j = 0; j < 3; j++) {
        int c = lane + 32 * j;
        float v = 0.f;
#pragma unroll
        for (int h = 0; h < NH; h++) v = fmaf(alpha[h], xls[h * 96 + c], v);
        atomicAdd(&hmean[(size_t)d * HID + c], v * (1.f / 6.f));
    }
}

// ---------------- node update ----------------
__global__ void nodeupd_kernel(const float* __restrict__ cb, const float* __restrict__ g,
                               const float* __restrict__ bt, int doElu,
                               const float* __restrict__ hmean, float* __restrict__ x, int M)
{
    int n    = (blockIdx.x * blockDim.x + threadIdx.x) >> 5;
    int lane = threadIdx.x & 31;
    if (n >= M) return;
    float v[3];
#pragma unroll
    for (int j = 0; j < 3; j++) {
        int c = lane + 32 * j;
        float hv = hmean[(size_t)n * HID + c] + cb[c];
        if (doElu) hv = (hv > 0.f) ? hv : (expf(hv) - 1.f);
        v[j] = hv;
    }
    float mu = warpsum32(v[0] + v[1] + v[2]) * (1.f / 96.f);
    float q = 0.f;
#pragma unroll
    for (int j = 0; j < 3; j++) { float d = v[j] - mu; q = fmaf(d, d, q); }
    float rstd = rsqrtf(warpsum32(q) * (1.f / 96.f) + 1e-5f);
#pragma unroll
    for (int j = 0; j < 3; j++) {
        int c = lane + 32 * j;
        float y = (v[j] - mu) * rstd * g[c] + bt[c];
        x[(size_t)n * HID + c] += y;
    }
}

// ---------------- persistent fused predictor MLP ----------------
#define PF_P1W 36864
#define PF_P3W 64
#define PF_C1  384
#define PF_C2  192
#define PF_CTX_U64 (32 * 288)
#define PRED_SMEM ((PF_P1W + PF_P3W + PF_C1 + PF_C2) * 4 + PF_CTX_U64 * 8)

__global__ __launch_bounds__(256) void predictor_kernel(
    const int* __restrict__ src, const int* __restrict__ dst,
    const float* __restrict__ xnode, const float* __restrict__ eemb,
    const float* __restrict__ p1w, const float* __restrict__ p1b,
    const float* __restrict__ p1g, const float* __restrict__ p1bt,
    const float* __restrict__ p2w, const float* __restrict__ p2b,
    const float* __restrict__ p2g, const float* __restrict__ p2bt,
    const float* __restrict__ p3w, const float* __restrict__ p3b,
    float* __restrict__ out, int E)
{
    extern __shared__ float sm[];
    float* s_p1w = sm;
    float* s_p3w = s_p1w + PF_P1W;
    float* s_c1  = s_p3w + PF_P3W;
    float* s_c2  = s_c1 + PF_C1;
    ull*   s_ctx = (ull*)(s_c2 + PF_C2);

    int tid = threadIdx.x;
    for (int i = tid; i < PF_P1W / 4; i += 256) ((float4*)s_p1w)[i] = ((const float4*)p1w)[i];
    if (tid < 64) s_p3w[tid] = p3w[tid];
    if (tid < 128) { s_c1[tid] = p1b[tid]; s_c1[128 + tid] = p1g[tid]; s_c1[256 + tid] = p1bt[tid]; }
    if (tid < 64)  { s_c2[tid] = p2b[tid]; s_c2[64 + tid] = p2g[tid]; s_c2[128 + tid] = p2bt[tid]; }
    float pb = p3b[0];

    int w = tid >> 5, lane = tid & 31;
    int j1 = lane * 4;
    int j2 = lane * 2;
    int NB = (E + 63) / 64;

    for (int bb = blockIdx.x; bb < NB; bb += gridDim.x) {
        __syncthreads();
        for (int i = tid; i < 64 * 72; i += 256) {
            int el = i / 72, kq = (i - el * 72) * 4;
            int e = bb * 64 + el; if (e > E - 1) e = E - 1;
            float4 v;
            if (kq < 96)       v = *(const float4*)(xnode + (size_t)src[e] * HID + kq);
            else if (kq < 192) v = *(const float4*)(xnode + (size_t)dst[e] * HID + (kq - 96));
            else               v = *(const float4*)(eemb + (size_t)e * HID + (kq - 192));
            float* base = (float*)(s_ctx + (size_t)(el >> 1) * 288 + kq);
            int hoff = el & 1;
            base[0 + hoff] = v.x; base[2 + hoff] = v.y;
            base[4 + hoff] = v.z; base[6 + hoff] = v.w;
        }
        __syncthreads();

        const ull* cp0 = s_ctx + (size_t)(4 * w + 0) * 288;
        const ull* cp1 = s_ctx + (size_t)(4 * w + 1) * 288;
        const ull* cp2 = s_ctx + (size_t)(4 * w + 2) * 288;
        const ull* cp3 = s_ctx + (size_t)(4 * w + 3) * 288;

        ull acc1[4][4];
#pragma unroll
        for (int q = 0; q < 4; q++)
#pragma unroll
            for (int j = 0; j < 4; j++) acc1[q][j] = 0ull;

#pragma unroll 4
        for (int k = 0; k < 288; k++) {
            ull c0 = cp0[k], c1 = cp1[k], c2 = cp2[k], c3 = cp3[k];
            float4 wv = *(const float4*)(s_p1w + k * 128 + j1);
            ull w0 = dup2(wv.x), w1 = dup2(wv.y), w2 = dup2(wv.z), w3 = dup2(wv.w);
            acc1[0][0] = fma2(c0, w0, acc1[0][0]); acc1[0][1] = fma2(c0, w1, acc1[0][1]);
            acc1[0][2] = fma2(c0, w2, acc1[0][2]); acc1[0][3] = fma2(c0, w3, acc1[0][3]);
            acc1[1][0] = fma2(c1, w0, acc1[1][0]); acc1[1][1] = fma2(c1, w1, acc1[1][1]);
            acc1[1][2] = fma2(c1, w2, acc1[1][2]); acc1[1][3] = fma2(c1, w3, acc1[1][3]);
            acc1[2][0] = fma2(c2, w0, acc1[2][0]); acc1[2][1] = fma2(c2, w1, acc1[2][1]);
            acc1[2][2] = fma2(c2, w2, acc1[2][2]); acc1[2][3] = fma2(c2, w3, acc1[2][3]);
            acc1[3][0] = fma2(c3, w0, acc1[3][0]); acc1[3][1] = fma2(c3, w1, acc1[3][1]);
            acc1[3][2] = fma2(c3, w2, acc1[3][2]); acc1[3][3] = fma2(c3, w3, acc1[3][3]);
        }

        float hE[4][4], hO[4][4];
#pragma unroll
        for (int q = 0; q < 4; q++)
#pragma unroll
            for (int j = 0; j < 4; j++) {
                float2 u = unpack2(acc1[q][j]);
                hE[q][j] = u.x + s_c1[j1 + j];
                hO[q][j] = u.y + s_c1[j1 + j];
            }
#pragma unroll
        for (int q = 0; q < 4; q++) {
            float sE = hE[q][0] + hE[q][1] + hE[q][2] + hE[q][3];
            float sO = hO[q][0] + hO[q][1] + hO[q][2] + hO[q][3];
            float muE = warpsum32(sE) * (1.f / 128.f);
            float muO = warpsum32(sO) * (1.f / 128.f);
            float qE = 0.f, qO = 0.f;
#pragma unroll
            for (int j = 0; j < 4; j++) {
                float d;
                d = hE[q][j] - muE; qE = fmaf(d, d, qE);
                d = hO[q][j] - muO; qO = fmaf(d, d, qO);
            }
            float rE = rsqrtf(warpsum32(qE) * (1.f / 128.f) + 1e-5f);
            float rO = rsqrtf(warpsum32(qO) * (1.f / 128.f) + 1e-5f);
#pragma unroll
            for (int j = 0; j < 4; j++) {
                float gma = s_c1[128 + j1 + j], bta = s_c1[256 + j1 + j];
                hE[q][j] = fmaxf((hE[q][j] - muE) * rE * gma + bta, 0.f);
                hO[q][j] = fmaxf((hO[q][j] - muO) * rO * gma + bta, 0.f);
            }
        }
        __syncwarp();
#pragma unroll
        for (int q = 0; q < 4; q++) {
            ull* hp = s_ctx + (size_t)(4 * w + q) * 288;
#pragma unroll
            for (int j = 0; j < 4; j++)
                hp[j1 + j] = pack2(hE[q][j], hO[q][j]);
        }
        __syncwarp();

        ull acc2[4][2];
#pragma unroll
        for (int q = 0; q < 4; q++) { acc2[q][0] = 0ull; acc2[q][1] = 0ull; }
#pragma unroll 4
        for (int k = 0; k < 128; k++) {
            ull c0 = cp0[k], c1 = cp1[k], c2 = cp2[k], c3 = cp3[k];
            float2 wv = __ldg((const float2*)(p2w + k * 64 + j2));
            ull w0 = dup2(wv.x), w1 = dup2(wv.y);
            acc2[0][0] = fma2(c0, w0, acc2[0][0]); acc2[0][1] = fma2(c0, w1, acc2[0][1]);
            acc2[1][0] = fma2(c1, w0, acc2[1][0]); acc2[1][1] = fma2(c1, w1, acc2[1][1]);
            acc2[2][0] = fma2(c2, w0, acc2[2][0]); acc2[2][1] = fma2(c2, w1, acc2[2][1]);
            acc2[3][0] = fma2(c3, w0, acc2[3][0]); acc2[3][1] = fma2(c3, w1, acc2[3][1]);
        }

        float gEo[4][2], gOo[4][2];
#pragma unroll
        for (int q = 0; q < 4; q++)
#pragma unroll
            for (int j = 0; j < 2; j++) {
                float2 u = unpack2(acc2[q][j]);
                gEo[q][j] = u.x + s_c2[j2 + j];
                gOo[q][j] = u.y + s_c2[j2 + j];
            }
#pragma unroll
        for (int q = 0; q < 4; q++) {
            float sE = gEo[q][0] + gEo[q][1];
            float sO = gOo[q][0] + gOo[q][1];
            float muE = warpsum32(sE) * (1.f / 64.f);
            float muO = warpsum32(sO) * (1.f / 64.f);
            float qE = 0.f, qO = 0.f;
#pragma unroll
            for (int j = 0; j < 2; j++) {
                float d;
                d = gEo[q][j] - muE; qE = fmaf(d, d, qE);
                d = gOo[q][j] - muO; qO = fmaf(d, d, qO);
            }
            float rE = rsqrtf(warpsum32(qE) * (1.f / 64.f) + 1e-5f);
            float rO = rsqrtf(warpsum32(qO) * (1.f / 64.f) + 1e-5f);
            float oE = 0.f, oO = 0.f;
#pragma unroll
            for (int j = 0; j < 2; j++) {
                float gma = s_c2[64 + j2 + j], bta = s_c2[128 + j2 + j];
                float vE = fmaxf((gEo[q][j] - muE) * rE * gma + bta, 0.f);
                float vO = fmaxf((gOo[q][j] - muO) * rO * gma + bta, 0.f);
                float w3v = s_p3w[j2 + j];
                oE = fmaf(vE, w3v, oE);
                oO = fmaf(vO, w3v, oO);
            }
            oE = warpsum32(oE);
            oO = warpsum32(oO);
            if (lane == 0) {
                int e0 = bb * 64 + 8 * w + 2 * q;
                if (e0 < E) out[e0] = oE + pb;
                if (e0 + 1 < E) out[e0 + 1] = oO + pb;
            }
        }
    }
}

// ---------------- launch ----------------
extern "C" void kernel_launch(void* const* d_in, const int* in_sizes, int n_in,
                              void* d_out, int out_size)
{
    const float* x         = (const float*)d_in[0];
    const float* edge_attr = (const float*)d_in[1];
    const int*   edge_idx  = (const int*)d_in[2];
    const float* ne_w = (const float*)d_in[3];
    const float* ne_b = (const float*)d_in[4];
    const float* ne_g = (const float*)d_in[5];
    const float* ne_bt = (const float*)d_in[6];
    const float* ee_w = (const float*)d_in[7];
    const float* ee_b = (const float*)d_in[8];
    const float* ee_g = (const float*)d_in[9];
    const float* ee_bt = (const float*)d_in[10];
    const float* Wl = (const float*)d_in[11];
    const float* bl = (const float*)d_in[12];
    const float* Wr = (const float*)d_in[13];
    const float* br = (const float*)d_in[14];
    const float* We = (const float*)d_in[15];
    const float* attw = (const float*)d_in[16];
    const float* cbias = (const float*)d_in[17];
    const float* lng = (const float*)d_in[18];
    const float* lnb = (const float*)d_in[19];
    const float* p1w = (const float*)d_in[20];
    const float* p1b = (const float*)d_in[21];
    const float* p1g = (const float*)d_in[22];
    const float* p1bt = (const float*)d_in[23];
    const float* p2w = (const float*)d_in[24];
    const float* p2b = (const float*)d_in[25];
    const float* p2g = (const float*)d_in[26];
    const float* p2bt = (const float*)d_in[27];
    const float* p3w = (const float*)d_in[28];
    const float* p3b = (const float*)d_in[29];

    int Nn = in_sizes[0] / 4;
    int E  = in_sizes[1] / 3;
    const int* srcp = edge_idx;
    const int* dstp = edge_idx + E;
    float* outp = (float*)d_out;

    void *px_, *pe_, *pxl_, *pxr_, *plog_, *pumax_, *pden_, *phm_;
    cudaGetSymbolAddress(&px_, g_x);
    cudaGetSymbolAddress(&pe_, g_eemb);
    cudaGetSymbolAddress(&pxl_, g_xl);
    cudaGetSymbolAddress(&pxr_, g_xr);
    cudaGetSymbolAddress(&plog_, g_logits);
    cudaGetSymbolAddress(&pumax_, g_umax);
    cudaGetSymbolAddress(&pden_, g_den);
    cudaGetSymbolAddress(&phm_, g_hmean);
    float* px = (float*)px_;   float* pe = (float*)pe_;
    float* pxl = (float*)pxl_; float* pxr = (float*)pxr_;
    float* plog = (float*)plog_;
    unsigned* pumax = (unsigned*)pumax_;
    float* pden = (float*)pden_; float* phm = (float*)phm_;

    cudaFuncSetAttribute(tf32_gemm_kernel<false>,
                         cudaFuncAttributeMaxDynamicSharedMemorySize, TF_SMEM);
    cudaFuncSetAttribute(tf32_gemm_kernel<true>,
                         cudaFuncAttributeMaxDynamicSharedMemorySize, TF_SMEM);
    cudaFuncSetAttribute(predictor_kernel,
                         cudaFuncAttributeMaxDynamicSharedMemorySize, PRED_SMEM);

    encoder_kernel<<<(Nn + 7) / 8, 256>>>(x, 4, ne_w, ne_b, ne_g, ne_bt, px, Nn);
    encoder_kernel<<<(E + 7) / 8, 256>>>(edge_attr, 3, ee_w, ee_b, ee_g, ee_bt, pe, E);

    dim3 gNt((Nn + 127) / 128, HC / 96);
    dim3 gEt((E + 127) / 128, HC / 96);

    for (int l = 0; l < 3; l++) {
        const float* Wl_l = Wl + (size_t)l * 96 * HC;
        const float* Wr_l = Wr + (size_t)l * 96 * HC;
        const float* We_l = We + (size_t)l * 96 * HC;
        tf32_gemm_kernel<false><<<gNt, 384, TF_SMEM>>>(px, Wl_l, bl + l * HC, pxl, Nn,
                                                       0, 0, 0, 0, 0, 0);
        tf32_gemm_kernel<false><<<gNt, 384, TF_SMEM>>>(px, Wr_l, br + l * HC, pxr, Nn,
                                                       0, 0, 0, 0, 0, 0);

        cudaMemsetAsync(plog, 0, (size_t)E * NH * sizeof(float), 0);
        cudaMemsetAsync(pumax, 0, (size_t)Nn * NH * sizeof(unsigned), 0);
        cudaMemsetAsync(pden, 0, (size_t)Nn * NH * sizeof(float), 0);
        cudaMemsetAsync(phm, 0, (size_t)Nn * HID * sizeof(float), 0);

        tf32_gemm_kernel<true><<<gEt, 384, TF_SMEM>>>(pe, We_l, (const float*)0, (float*)0, E,
                                                      srcp, dstp, pxl, pxr,
                                                      attw + l * NH * 96, plog);

        segmax_kernel<<<(E * NH + 255) / 256, 256>>>(dstp, plog, pumax, E);
        expsum_kernel<<<(E * NH + 255) / 256, 256>>>(dstp, plog, pumax, pden, E);
        agg_kernel<<<(E + 7) / 8, 256>>>(srcp, dstp, plog, pden, pxl, phm, E);
        nodeupd_kernel<<<(Nn + 7) / 8, 256>>>(cbias + l * HID, lng + l * HID,
                                              lnb + l * HID, (l < 2) ? 1 : 0, phm, px, Nn);
    }

    predictor_kernel<<<148, 256, PRED_SMEM>>>(
        srcp, dstp, px, pe,
        p1w, p1b, p1g, p1bt, p2w, p2b, p2g, p2bt, p3w, p3b, outp, E);
}

// round 8
// speedup vs baseline: 1.8743x; 1.0112x over previous
#include <cuda_runtime.h>
#include <math.h>

#define HID 96
#define HC  576
#define NH  6

typedef unsigned long long ull;

// ---------------- f32x2 packed helpers ----------------
__device__ __forceinline__ ull fma2(ull a, ull b, ull c) {
    ull d;
    asm("fma.rn.f32x2 %0, %1, %2, %3;" : "=l"(d) : "l"(a), "l"(b), "l"(c));
    return d;
}
__device__ __forceinline__ ull pack2(float x, float y) {
    ull r;
    asm("mov.b64 %0, {%1, %2};" : "=l"(r) : "f"(x), "f"(y));
    return r;
}
__device__ __forceinline__ ull dup2(float x) { return pack2(x, x); }
__device__ __forceinline__ float2 unpack2(ull v) {
    float2 r;
    asm("mov.b64 {%0, %1}, %2;" : "=f"(r.x), "=f"(r.y) : "l"(v));
    return r;
}
__device__ __forceinline__ unsigned f2tf32(float f) {
    unsigned r;
    asm("cvt.rna.tf32.f32 %0, %1;" : "=r"(r) : "f"(f));
    return r;
}
__device__ __forceinline__ ull pack_tf32(float a, float b) {
    unsigned lo = f2tf32(a), hi = f2tf32(b);
    ull r;
    asm("mov.b64 %0, {%1, %2};" : "=l"(r) : "r"(lo), "r"(hi));
    return r;
}
__device__ __forceinline__ void mma_tf32(float c[4],
    unsigned a0, unsigned a1, unsigned a2, unsigned a3,
    unsigned b0, unsigned b1)
{
    asm("mma.sync.aligned.m16n8k8.row.col.f32.tf32.tf32.f32 "
        "{%0,%1,%2,%3},{%4,%5,%6,%7},{%8,%9},{%0,%1,%2,%3};"
        : "+f"(c[0]), "+f"(c[1]), "+f"(c[2]), "+f"(c[3])
        : "r"(a0), "r"(a1), "r"(a2), "r"(a3), "r"(b0), "r"(b1));
}
__device__ __forceinline__ void red_add_v4(float* p, float4 v) {
    asm volatile("red.global.add.v4.f32 [%0], {%1, %2, %3, %4};"
                 :: "l"(p), "f"(v.x), "f"(v.y), "f"(v.z), "f"(v.w) : "memory");
}

// ---------------- scratch ----------------
__device__ float    g_x[20000 * HID];
__device__ float    g_eemb[200000 * HID];
__device__ float    g_xl[20000 * HC];
__device__ float    g_xr[20000 * HC];
__device__ float    g_logits[200000 * NH];
__device__ unsigned g_umax[20000 * NH];
__device__ float    g_den[20000 * NH];
__device__ float    g_hmean[20000 * HID];

__device__ __forceinline__ float warpsum32(float v) {
#pragma unroll
    for (int m = 16; m; m >>= 1) v += __shfl_xor_sync(0xffffffffu, v, m);
    return v;
}

// ---------------- encoder ----------------
__global__ void encoder_kernel(const float* __restrict__ in, int Fin,
                               const float* __restrict__ W, const float* __restrict__ b,
                               const float* __restrict__ g, const float* __restrict__ beta,
                               float* __restrict__ out, int M)
{
    int w    = (blockIdx.x * blockDim.x + threadIdx.x) >> 5;
    int lane = threadIdx.x & 31;
    if (w >= M) return;
    float xin[4];
#pragma unroll
    for (int k = 0; k < 4; k++) xin[k] = (k < Fin) ? in[(size_t)w * Fin + k] : 0.f;
    float v[3];
#pragma unroll
    for (int j = 0; j < 3; j++) {
        int c = lane + 32 * j;
        float acc = b[c];
        for (int k = 0; k < Fin; k++) acc = fmaf(xin[k], W[k * HID + c], acc);
        v[j] = acc;
    }
    float mu = warpsum32(v[0] + v[1] + v[2]) * (1.f / 96.f);
    float q = 0.f;
#pragma unroll
    for (int j = 0; j < 3; j++) { float d = v[j] - mu; q = fmaf(d, d, q); }
    float rstd = rsqrtf(warpsum32(q) * (1.f / 96.f) + 1e-5f);
#pragma unroll
    for (int j = 0; j < 3; j++) {
        int c = lane + 32 * j;
        float y = (v[j] - mu) * rstd * g[c] + beta[c];
        out[(size_t)w * HID + c] = fmaxf(y, 0.f);
    }
}

// ---------------- node tf32 GEMM: C[M,576] = A[M,96] @ B[96,576] + bias ------
// tile 128x96, 12 warps (4m x 3n), m16n8k8 tf32, packed-pair smem (R7 proven).
#define AU_ULL (12 * 512)
#define BU_ULL (12 * 384)
#define TF_SMEM ((AU_ULL + BU_ULL) * 8)

__global__ __launch_bounds__(384) void tf32_gemm_kernel(
    const float* __restrict__ Ag, const float* __restrict__ Bg,
    const float* __restrict__ bias, float* __restrict__ C, int M)
{
    extern __shared__ ull sh64[];
    ull* Au = sh64;
    ull* Bu = sh64 + AU_ULL;

    int tid = threadIdx.x;
    int m0 = blockIdx.x * 128, n0 = blockIdx.y * 96;

    {
        int row = tid & 127;
        int kg  = tid >> 7;
        int m = m0 + row;
        const float* arow = Ag + (size_t)m * 96;
#pragma unroll
        for (int i = 0; i < 4; i++) {
            int ks = kg * 4 + i;
            float4 lo = make_float4(0.f, 0.f, 0.f, 0.f);
            float4 hi = make_float4(0.f, 0.f, 0.f, 0.f);
            if (m < M) {
                lo = *(const float4*)(arow + ks * 8);
                hi = *(const float4*)(arow + ks * 8 + 4);
            }
            ull* dstp = Au + ks * 512 + row * 4;
            *(ulonglong2*)(dstp)     = make_ulonglong2(pack_tf32(lo.x, hi.x), pack_tf32(lo.y, hi.y));
            *(ulonglong2*)(dstp + 2) = make_ulonglong2(pack_tf32(lo.z, hi.z), pack_tf32(lo.w, hi.w));
        }
    }
    for (int t = tid; t < 1152; t += 384) {
        int ks  = t / 96;
        int rem = t - ks * 96;
        int q = rem >> 2;
        int r = rem & 3;
        int krow = ks * 8 + r;
        const float* b0 = Bg + (size_t)krow * HC + n0 + q * 4;
        float4 lo = *(const float4*)b0;
        float4 hi = *(const float4*)(b0 + 4 * HC);
        ull* dstb = Bu + ks * 384 + q * 16 + r;
        dstb[0]  = pack_tf32(lo.x, hi.x);
        dstb[4]  = pack_tf32(lo.y, hi.y);
        dstb[8]  = pack_tf32(lo.z, hi.z);
        dstb[12] = pack_tf32(lo.w, hi.w);
    }
    __syncthreads();

    int wid = tid >> 5, lane = tid & 31;
    int wm = wid & 3, wn = wid >> 2;
    int g = lane >> 2, tig = lane & 3;
    int rowb = wm * 32, colb = wn * 32;

    float acc[2][4][4];
#pragma unroll
    for (int mt = 0; mt < 2; mt++)
#pragma unroll
        for (int nt = 0; nt < 4; nt++)
#pragma unroll
            for (int q = 0; q < 4; q++) acc[mt][nt][q] = 0.f;

#pragma unroll
    for (int ks = 0; ks < 12; ks++) {
        const ull* Ak = Au + ks * 512;
        const ull* Bk = Bu + ks * 384;
        uint2 pa[2][2];
#pragma unroll
        for (int mt = 0; mt < 2; mt++) {
            int rb = rowb + mt * 16 + g;
            pa[mt][0] = *(const uint2*)(Ak + rb * 4 + tig);
            pa[mt][1] = *(const uint2*)(Ak + (rb + 8) * 4 + tig);
        }
#pragma unroll
        for (int nt = 0; nt < 4; nt++) {
            int cb = colb + nt * 8 + g;
            uint2 pb = *(const uint2*)(Bk + cb * 4 + tig);
#pragma unroll
            for (int mt = 0; mt < 2; mt++)
                mma_tf32(acc[mt][nt],
                         pa[mt][0].x, pa[mt][1].x, pa[mt][0].y, pa[mt][1].y,
                         pb.x, pb.y);
        }
    }

#pragma unroll
    for (int nt = 0; nt < 4; nt++) {
        int c = n0 + colb + nt * 8 + 2 * tig;
        float2 bq = *(const float2*)(bias + c);
#pragma unroll
        for (int mt = 0; mt < 2; mt++) {
            int r0 = m0 + rowb + mt * 16 + g;
            if (r0 < M) {
                float2 o = make_float2(acc[mt][nt][0] + bq.x, acc[mt][nt][1] + bq.y);
                *(float2*)(C + (size_t)r0 * HC + c) = o;
            }
            int r1 = r0 + 8;
            if (r1 < M) {
                float2 o = make_float2(acc[mt][nt][2] + bq.x, acc[mt][nt][3] + bq.y);
                *(float2*)(C + (size_t)r1 * HC + c) = o;
            }
        }
    }
}

// ---------------- fused edge kernel: all 6 heads per block ----------------
// tile 128 edges x 576 cols (looped per head, double-buffered B), A staged once.
// logits accumulated in smem -> plain stores + fused segment-max.
#define EAU (12 * 512)
#define EBU (12 * 384)
#define EDGE_SMEM ((EAU + 2 * EBU) * 8 + 128 * 8 * 4 + 128 * 2 * 4)

__global__ __launch_bounds__(384) void edge_fused_kernel(
    const float* __restrict__ Ag, const float* __restrict__ Bg, int M,
    const int* __restrict__ src, const int* __restrict__ dst,
    const float* __restrict__ xl, const float* __restrict__ xr,
    const float* __restrict__ attw, float* __restrict__ logits,
    unsigned* __restrict__ umax)
{
    extern __shared__ ull sh64[];
    ull* Au  = sh64;
    ull* Bu0 = sh64 + EAU;
    ull* Bu1 = Bu0 + EBU;
    float* s_logit = (float*)(Bu1 + EBU);        // [128][8] padded
    int*   s_src   = (int*)(s_logit + 128 * 8);  // [128]
    int*   s_dst   = s_src + 128;

    int tid = threadIdx.x;
    int m0 = blockIdx.x * 128;

    for (int i = tid; i < 128 * 8; i += 384) s_logit[i] = 0.f;
    if (tid < 128) {
        int e = m0 + tid;
        int ec = (e < M) ? e : (M - 1);
        s_src[tid] = src[ec];
        s_dst[tid] = dst[ec];
    }

    // stage A once
    {
        int row = tid & 127;
        int kg  = tid >> 7;
        int m = m0 + row;
        const float* arow = Ag + (size_t)m * 96;
#pragma unroll
        for (int i = 0; i < 4; i++) {
            int ks = kg * 4 + i;
            float4 lo = make_float4(0.f, 0.f, 0.f, 0.f);
            float4 hi = make_float4(0.f, 0.f, 0.f, 0.f);
            if (m < M) {
                lo = *(const float4*)(arow + ks * 8);
                hi = *(const float4*)(arow + ks * 8 + 4);
            }
            ull* dstp = Au + ks * 512 + row * 4;
            *(ulonglong2*)(dstp)     = make_ulonglong2(pack_tf32(lo.x, hi.x), pack_tf32(lo.y, hi.y));
            *(ulonglong2*)(dstp + 2) = make_ulonglong2(pack_tf32(lo.z, hi.z), pack_tf32(lo.w, hi.w));
        }
    }
    // stage B head 0
    for (int t = tid; t < 1152; t += 384) {
        int ks  = t / 96;
        int rem = t - ks * 96;
        int q = rem >> 2, r = rem & 3;
        const float* b0 = Bg + (size_t)(ks * 8 + r) * HC + q * 4;
        float4 lo = *(const float4*)b0;
        float4 hi = *(const float4*)(b0 + 4 * HC);
        ull* dstb = Bu0 + ks * 384 + q * 16 + r;
        dstb[0]  = pack_tf32(lo.x, hi.x);
        dstb[4]  = pack_tf32(lo.y, hi.y);
        dstb[8]  = pack_tf32(lo.z, hi.z);
        dstb[12] = pack_tf32(lo.w, hi.w);
    }
    __syncthreads();

    int wid = tid >> 5, lane = tid & 31;
    int wm = wid & 3, wn = wid >> 2;
    int g = lane >> 2, tig = lane & 3;
    int rowb = wm * 32, colb = wn * 32;

    for (int h = 0; h < NH; h++) {
        ull* Bcur = (h & 1) ? Bu1 : Bu0;
        // prefetch next head's B into registers
        float4 plo[3], phi[3];
        if (h < 5) {
#pragma unroll
            for (int it = 0; it < 3; it++) {
                int t = tid + 384 * it;
                int ks  = t / 96;
                int rem = t - ks * 96;
                int q = rem >> 2, r = rem & 3;
                const float* b0 = Bg + (size_t)(ks * 8 + r) * HC + (h + 1) * 96 + q * 4;
                plo[it] = *(const float4*)b0;
                phi[it] = *(const float4*)(b0 + 4 * HC);
            }
        }

        float acc[2][4][4];
#pragma unroll
        for (int mt = 0; mt < 2; mt++)
#pragma unroll
            for (int nt = 0; nt < 4; nt++)
#pragma unroll
                for (int q = 0; q < 4; q++) acc[mt][nt][q] = 0.f;

#pragma unroll
        for (int ks = 0; ks < 12; ks++) {
            const ull* Ak = Au + ks * 512;
            const ull* Bk = Bcur + ks * 384;
            uint2 pa[2][2];
#pragma unroll
            for (int mt = 0; mt < 2; mt++) {
                int rb = rowb + mt * 16 + g;
                pa[mt][0] = *(const uint2*)(Ak + rb * 4 + tig);
                pa[mt][1] = *(const uint2*)(Ak + (rb + 8) * 4 + tig);
            }
#pragma unroll
            for (int nt = 0; nt < 4; nt++) {
                int cb = colb + nt * 8 + g;
                uint2 pb = *(const uint2*)(Bk + cb * 4 + tig);
#pragma unroll
                for (int mt = 0; mt < 2; mt++)
                    mma_tf32(acc[mt][nt],
                             pa[mt][0].x, pa[mt][1].x, pa[mt][0].y, pa[mt][1].y,
                             pb.x, pb.y);
            }
        }

        // epilogue: gather xl/xr, leaky-relu, dot attw, segmented reduce, smem acc
#pragma unroll
        for (int mt = 0; mt < 2; mt++) {
#pragma unroll
            for (int half = 0; half < 2; half++) {
                int ml = rowb + mt * 16 + half * 8 + g;
                int m = m0 + ml;
                float partial = 0.f;
                if (m < M) {
                    int s = s_src[ml], d = s_dst[ml];
                    const float* xls = xl + (size_t)s * HC;
                    const float* xrd = xr + (size_t)d * HC;
#pragma unroll
                    for (int nt = 0; nt < 4; nt++) {
                        int c = h * 96 + colb + nt * 8 + 2 * tig;
                        float2 xlv = *(const float2*)(xls + c);
                        float2 xrv = *(const float2*)(xrd + c);
                        float aw0 = attw[c], aw1 = attw[c + 1];
                        float a0 = acc[mt][nt][half * 2 + 0];
                        float a1 = acc[mt][nt][half * 2 + 1];
                        float t0 = a0 + xlv.x + xrv.x; t0 = (t0 > 0.f) ? t0 : 0.2f * t0;
                        float t1 = a1 + xlv.y + xrv.y; t1 = (t1 > 0.f) ? t1 : 0.2f * t1;
                        partial = fmaf(t0, aw0, fmaf(t1, aw1, partial));
                    }
                }
                partial += __shfl_down_sync(0xffffffffu, partial, 1, 4);
                partial += __shfl_down_sync(0xffffffffu, partial, 2, 4);
                if (tig == 0 && m < M)
                    atomicAdd(&s_logit[ml * 8 + h], partial);
            }
        }

        if (h < 5) {
            ull* Bnext = (h & 1) ? Bu0 : Bu1;
#pragma unroll
            for (int it = 0; it < 3; it++) {
                int t = tid + 384 * it;
                int ks  = t / 96;
                int rem = t - ks * 96;
                int q = rem >> 2, r = rem & 3;
                ull* dstb = Bnext + ks * 384 + q * 16 + r;
                dstb[0]  = pack_tf32(plo[it].x, phi[it].x);
                dstb[4]  = pack_tf32(plo[it].y, phi[it].y);
                dstb[8]  = pack_tf32(plo[it].z, phi[it].z);
                dstb[12] = pack_tf32(plo[it].w, phi[it].w);
            }
        }
        __syncthreads();
    }

    // write logits + fused segment-max
    for (int t = tid; t < 128 * NH; t += 384) {
        int el = t / NH, h = t - el * NH;
        int e = m0 + el;
        if (e < M) {
            float lg = s_logit[el * 8 + h];
            logits[(size_t)e * NH + h] = lg;
            unsigned u = __float_as_uint(lg);
            u ^= (u >> 31) ? 0xFFFFFFFFu : 0x80000000u;
            atomicMax(&umax[s_dst[el] * NH + h], u);
        }
    }
}

// ---------------- exp + denominator ----------------
__global__ void expsum_kernel(const int* __restrict__ dst, float* __restrict__ logits,
                              const unsigned* __restrict__ umax, float* __restrict__ den, int E)
{
    int t = blockIdx.x * blockDim.x + threadIdx.x;
    if (t >= E * NH) return;
    int e = t / NH, h = t - e * NH;
    int d = dst[e];
    unsigned u = umax[d * NH + h];
    float m = (u & 0x80000000u) ? __uint_as_float(u ^ 0x80000000u) : __uint_as_float(~u);
    float ex = expf(logits[t] - m);
    logits[t] = ex;
    atomicAdd(&den[d * NH + h], ex);
}

// ---------------- aggregate (red.v4) ----------------
__global__ void agg_kernel(const int* __restrict__ src, const int* __restrict__ dst,
                           const float* __restrict__ ex, const float* __restrict__ den,
                           const float* __restrict__ xl, float* __restrict__ hmean, int E)
{
    int e    = (blockIdx.x * blockDim.x + threadIdx.x) >> 5;
    int lane = threadIdx.x & 31;
    if (e >= E) return;
    int s = src[e], d = dst[e];
    float a = 0.f;
    if (lane < NH) a = ex[e * NH + lane] / (den[d * NH + lane] + 1e-16f);
    float alpha[NH];
#pragma unroll
    for (int h = 0; h < NH; h++) alpha[h] = __shfl_sync(0xffffffffu, a, h) * (1.f / 6.f);
    if (lane < 24) {
        const float* xls = xl + (size_t)s * HC + lane * 4;
        float4 v = make_float4(0.f, 0.f, 0.f, 0.f);
#pragma unroll
        for (int h = 0; h < NH; h++) {
            float4 xv = *(const float4*)(xls + h * 96);
            v.x = fmaf(alpha[h], xv.x, v.x);
            v.y = fmaf(alpha[h], xv.y, v.y);
            v.z = fmaf(alpha[h], xv.z, v.z);
            v.w = fmaf(alpha[h], xv.w, v.w);
        }
        red_add_v4(hmean + (size_t)d * HID + lane * 4, v);
    }
}

// ---------------- node update ----------------
__global__ void nodeupd_kernel(const float* __restrict__ cb, const float* __restrict__ g,
                               const float* __restrict__ bt, int doElu,
                               const float* __restrict__ hmean, float* __restrict__ x, int M)
{
    int n    = (blockIdx.x * blockDim.x + threadIdx.x) >> 5;
    int lane = threadIdx.x & 31;
    if (n >= M) return;
    float v[3];
#pragma unroll
    for (int j = 0; j < 3; j++) {
        int c = lane + 32 * j;
        float hv = hmean[(size_t)n * HID + c] + cb[c];
        if (doElu) hv = (hv > 0.f) ? hv : (expf(hv) - 1.f);
        v[j] = hv;
    }
    float mu = warpsum32(v[0] + v[1] + v[2]) * (1.f / 96.f);
    float q = 0.f;
#pragma unroll
    for (int j = 0; j < 3; j++) { float d = v[j] - mu; q = fmaf(d, d, q); }
    float rstd = rsqrtf(warpsum32(q) * (1.f / 96.f) + 1e-5f);
#pragma unroll
    for (int j = 0; j < 3; j++) {
        int c = lane + 32 * j;
        float y = (v[j] - mu) * rstd * g[c] + bt[c];
        x[(size_t)n * HID + c] += y;
    }
}

// ---------------- persistent fused predictor MLP ----------------
#define PF_P1W 36864
#define PF_P3W 64
#define PF_C1  384
#define PF_C2  192
#define PF_CTX_U64 (32 * 288)
#define PRED_SMEM ((PF_P1W + PF_P3W + PF_C1 + PF_C2) * 4 + PF_CTX_U64 * 8)

__global__ __launch_bounds__(256) void predictor_kernel(
    const int* __restrict__ src, const int* __restrict__ dst,
    const float* __restrict__ xnode, const float* __restrict__ eemb,
    const float* __restrict__ p1w, const float* __restrict__ p1b,
    const float* __restrict__ p1g, const float* __restrict__ p1bt,
    const float* __restrict__ p2w, const float* __restrict__ p2b,
    const float* __restrict__ p2g, const float* __restrict__ p2bt,
    const float* __restrict__ p3w, const float* __restrict__ p3b,
    float* __restrict__ out, int E)
{
    extern __shared__ float sm[];
    float* s_p1w = sm;
    float* s_p3w = s_p1w + PF_P1W;
    float* s_c1  = s_p3w + PF_P3W;
    float* s_c2  = s_c1 + PF_C1;
    ull*   s_ctx = (ull*)(s_c2 + PF_C2);

    int tid = threadIdx.x;
    for (int i = tid; i < PF_P1W / 4; i += 256) ((float4*)s_p1w)[i] = ((const float4*)p1w)[i];
    if (tid < 64) s_p3w[tid] = p3w[tid];
    if (tid < 128) { s_c1[tid] = p1b[tid]; s_c1[128 + tid] = p1g[tid]; s_c1[256 + tid] = p1bt[tid]; }
    if (tid < 64)  { s_c2[tid] = p2b[tid]; s_c2[64 + tid] = p2g[tid]; s_c2[128 + tid] = p2bt[tid]; }
    float pb = p3b[0];

    int w = tid >> 5, lane = tid & 31;
    int j1 = lane * 4;
    int j2 = lane * 2;
    int NB = (E + 63) / 64;

    for (int bb = blockIdx.x; bb < NB; bb += gridDim.x) {
        __syncthreads();
        for (int i = tid; i < 64 * 72; i += 256) {
            int el = i / 72, kq = (i - el * 72) * 4;
            int e = bb * 64 + el; if (e > E - 1) e = E - 1;
            float4 v;
            if (kq < 96)       v = *(const float4*)(xnode + (size_t)src[e] * HID + kq);
            else if (kq < 192) v = *(const float4*)(xnode + (size_t)dst[e] * HID + (kq - 96));
            else               v = *(const float4*)(eemb + (size_t)e * HID + (kq - 192));
            float* base = (float*)(s_ctx + (size_t)(el >> 1) * 288 + kq);
            int hoff = el & 1;
            base[0 + hoff] = v.x; base[2 + hoff] = v.y;
            base[4 + hoff] = v.z; base[6 + hoff] = v.w;
        }
        __syncthreads();

        const ull* cp0 = s_ctx + (size_t)(4 * w + 0) * 288;
        const ull* cp1 = s_ctx + (size_t)(4 * w + 1) * 288;
        const ull* cp2 = s_ctx + (size_t)(4 * w + 2) * 288;
        const ull* cp3 = s_ctx + (size_t)(4 * w + 3) * 288;

        ull acc1[4][4];
#pragma unroll
        for (int q = 0; q < 4; q++)
#pragma unroll
            for (int j = 0; j < 4; j++) acc1[q][j] = 0ull;

#pragma unroll 4
        for (int k = 0; k < 288; k++) {
            ull c0 = cp0[k], c1 = cp1[k], c2 = cp2[k], c3 = cp3[k];
            float4 wv = *(const float4*)(s_p1w + k * 128 + j1);
            ull w0 = dup2(wv.x), w1 = dup2(wv.y), w2 = dup2(wv.z), w3 = dup2(wv.w);
            acc1[0][0] = fma2(c0, w0, acc1[0][0]); acc1[0][1] = fma2(c0, w1, acc1[0][1]);
            acc1[0][2] = fma2(c0, w2, acc1[0][2]); acc1[0][3] = fma2(c0, w3, acc1[0][3]);
            acc1[1][0] = fma2(c1, w0, acc1[1][0]); acc1[1][1] = fma2(c1, w1, acc1[1][1]);
            acc1[1][2] = fma2(c1, w2, acc1[1][2]); acc1[1][3] = fma2(c1, w3, acc1[1][3]);
            acc1[2][0] = fma2(c2, w0, acc1[2][0]); acc1[2][1] = fma2(c2, w1, acc1[2][1]);
            acc1[2][2] = fma2(c2, w2, acc1[2][2]); acc1[2][3] = fma2(c2, w3, acc1[2][3]);
            acc1[3][0] = fma2(c3, w0, acc1[3][0]); acc1[3][1] = fma2(c3, w1, acc1[3][1]);
            acc1[3][2] = fma2(c3, w2, acc1[3][2]); acc1[3][3] = fma2(c3, w3, acc1[3][3]);
        }

        float hE[4][4], hO[4][4];
#pragma unroll
        for (int q = 0; q < 4; q++)
#pragma unroll
            for (int j = 0; j < 4; j++) {
                float2 u = unpack2(acc1[q][j]);
                hE[q][j] = u.x + s_c1[j1 + j];
                hO[q][j] = u.y + s_c1[j1 + j];
            }
#pragma unroll
        for (int q = 0; q < 4; q++) {
            float sE = hE[q][0] + hE[q][1] + hE[q][2] + hE[q][3];
            float sO = hO[q][0] + hO[q][1] + hO[q][2] + hO[q][3];
            float muE = warpsum32(sE) * (1.f / 128.f);
            float muO = warpsum32(sO) * (1.f / 128.f);
            float qE = 0.f, qO = 0.f;
#pragma unroll
            for (int j = 0; j < 4; j++) {
                float d;
                d = hE[q][j] - muE; qE = fmaf(d, d, qE);
                d = hO[q][j] - muO; qO = fmaf(d, d, qO);
            }
            float rE = rsqrtf(warpsum32(qE) * (1.f / 128.f) + 1e-5f);
            float rO = rsqrtf(warpsum32(qO) * (1.f / 128.f) + 1e-5f);
#pragma unroll
            for (int j = 0; j < 4; j++) {
                float gma = s_c1[128 + j1 + j], bta = s_c1[256 + j1 + j];
                hE[q][j] = fmaxf((hE[q][j] - muE) * rE * gma + bta, 0.f);
                hO[q][j] = fmaxf((hO[q][j] - muO) * rO * gma + bta, 0.f);
            }
        }
        __syncwarp();
#pragma unroll
        for (int q = 0; q < 4; q++) {
            ull* hp = s_ctx + (size_t)(4 * w + q) * 288;
#pragma unroll
            for (int j = 0; j < 4; j++)
                hp[j1 + j] = pack2(hE[q][j], hO[q][j]);
        }
        __syncwarp();

        ull acc2[4][2];
#pragma unroll
        for (int q = 0; q < 4; q++) { acc2[q][0] = 0ull; acc2[q][1] = 0ull; }
#pragma unroll 4
        for (int k = 0; k < 128; k++) {
            ull c0 = cp0[k], c1 = cp1[k], c2 = cp2[k], c3 = cp3[k];
            float2 wv = __ldg((const float2*)(p2w + k * 64 + j2));
            ull w0 = dup2(wv.x), w1 = dup2(wv.y);
            acc2[0][0] = fma2(c0, w0, acc2[0][0]); acc2[0][1] = fma2(c0, w1, acc2[0][1]);
            acc2[1][0] = fma2(c1, w0, acc2[1][0]); acc2[1][1] = fma2(c1, w1, acc2[1][1]);
            acc2[2][0] = fma2(c2, w0, acc2[2][0]); acc2[2][1] = fma2(c2, w1, acc2[2][1]);
            acc2[3][0] = fma2(c3, w0, acc2[3][0]); acc2[3][1] = fma2(c3, w1, acc2[3][1]);
        }

        float gEo[4][2], gOo[4][2];
#pragma unroll
        for (int q = 0; q < 4; q++)
#pragma unroll
            for (int j = 0; j < 2; j++) {
                float2 u = unpack2(acc2[q][j]);
                gEo[q][j] = u.x + s_c2[j2 + j];
                gOo[q][j] = u.y + s_c2[j2 + j];
            }
#pragma unroll
        for (int q = 0; q < 4; q++) {
            float sE = gEo[q][0] + gEo[q][1];
            float sO = gOo[q][0] + gOo[q][1];
            float muE = warpsum32(sE) * (1.f / 64.f);
            float muO = warpsum32(sO) * (1.f / 64.f);
            float qE = 0.f, qO = 0.f;
#pragma unroll
            for (int j = 0; j < 2; j++) {
                float d;
                d = gEo[q][j] - muE; qE = fmaf(d, d, qE);
                d = gOo[q][j] - muO; qO = fmaf(d, d, qO);
            }
            float rE = rsqrtf(warpsum32(qE) * (1.f / 64.f) + 1e-5f);
            float rO = rsqrtf(warpsum32(qO) * (1.f / 64.f) + 1e-5f);
            float oE = 0.f, oO = 0.f;
#pragma unroll
            for (int j = 0; j < 2; j++) {
                float gma = s_c2[64 + j2 + j], bta = s_c2[128 + j2 + j];
                float vE = fmaxf((gEo[q][j] - muE) * rE * gma + bta, 0.f);
                float vO = fmaxf((gOo[q][j] - muO) * rO * gma + bta, 0.f);
                float w3v = s_p3w[j2 + j];
                oE = fmaf(vE, w3v, oE);
                oO = fmaf(vO, w3v, oO);
            }
            oE = warpsum32(oE);
            oO = warpsum32(oO);
            if (lane == 0) {
                int e0 = bb * 64 + 8 * w + 2 * q;
                if (e0 < E) out[e0] = oE + pb;
                if (e0 + 1 < E) out[e0 + 1] = oO + pb;
            }
        }
    }
}

// ---------------- launch ----------------
extern "C" void kernel_launch(void* const* d_in, const int* in_sizes, int n_in,
                              void* d_out, int out_size)
{
    const float* x         = (const float*)d_in[0];
    const float* edge_attr = (const float*)d_in[1];
    const int*   edge_idx  = (const int*)d_in[2];
    const float* ne_w = (const float*)d_in[3];
    const float* ne_b = (const float*)d_in[4];
    const float* ne_g = (const float*)d_in[5];
    const float* ne_bt = (const float*)d_in[6];
    const float* ee_w = (const float*)d_in[7];
    const float* ee_b = (const float*)d_in[8];
    const float* ee_g = (const float*)d_in[9];
    const float* ee_bt = (const float*)d_in[10];
    const float* Wl = (const float*)d_in[11];
    const float* bl = (const float*)d_in[12];
    const float* Wr = (const float*)d_in[13];
    const float* br = (const float*)d_in[14];
    const float* We = (const float*)d_in[15];
    const float* attw = (const float*)d_in[16];
    const float* cbias = (const float*)d_in[17];
    const float* lng = (const float*)d_in[18];
    const float* lnb = (const float*)d_in[19];
    const float* p1w = (const float*)d_in[20];
    const float* p1b = (const float*)d_in[21];
    const float* p1g = (const float*)d_in[22];
    const float* p1bt = (const float*)d_in[23];
    const float* p2w = (const float*)d_in[24];
    const float* p2b = (const float*)d_in[25];
    const float* p2g = (const float*)d_in[26];
    const float* p2bt = (const float*)d_in[27];
    const float* p3w = (const float*)d_in[28];
    const float* p3b = (const float*)d_in[29];

    int Nn = in_sizes[0] / 4;
    int E  = in_sizes[1] / 3;
    const int* srcp = edge_idx;
    const int* dstp = edge_idx + E;
    float* outp = (float*)d_out;

    void *px_, *pe_, *pxl_, *pxr_, *plog_, *pumax_, *pden_, *phm_;
    cudaGetSymbolAddress(&px_, g_x);
    cudaGetSymbolAddress(&pe_, g_eemb);
    cudaGetSymbolAddress(&pxl_, g_xl);
    cudaGetSymbolAddress(&pxr_, g_xr);
    cudaGetSymbolAddress(&plog_, g_logits);
    cudaGetSymbolAddress(&pumax_, g_umax);
    cudaGetSymbolAddress(&pden_, g_den);
    cudaGetSymbolAddress(&phm_, g_hmean);
    float* px = (float*)px_;   float* pe = (float*)pe_;
    float* pxl = (float*)pxl_; float* pxr = (float*)pxr_;
    float* plog = (float*)plog_;
    unsigned* pumax = (unsigned*)pumax_;
    float* pden = (float*)pden_; float* phm = (float*)phm_;

    cudaFuncSetAttribute(tf32_gemm_kernel,
                         cudaFuncAttributeMaxDynamicSharedMemorySize, TF_SMEM);
    cudaFuncSetAttribute(edge_fused_kernel,
                         cudaFuncAttributeMaxDynamicSharedMemorySize, EDGE_SMEM);
    cudaFuncSetAttribute(predictor_kernel,
                         cudaFuncAttributeMaxDynamicSharedMemorySize, PRED_SMEM);

    encoder_kernel<<<(Nn + 7) / 8, 256>>>(x, 4, ne_w, ne_b, ne_g, ne_bt, px, Nn);
    encoder_kernel<<<(E + 7) / 8, 256>>>(edge_attr, 3, ee_w, ee_b, ee_g, ee_bt, pe, E);

    dim3 gNt((Nn + 127) / 128, HC / 96);
    int gEb = (E + 127) / 128;

    for (int l = 0; l < 3; l++) {
        const float* Wl_l = Wl + (size_t)l * 96 * HC;
        const float* Wr_l = Wr + (size_t)l * 96 * HC;
        const float* We_l = We + (size_t)l * 96 * HC;
        tf32_gemm_kernel<<<gNt, 384, TF_SMEM>>>(px, Wl_l, bl + l * HC, pxl, Nn);
        tf32_gemm_kernel<<<gNt, 384, TF_SMEM>>>(px, Wr_l, br + l * HC, pxr, Nn);

        cudaMemsetAsync(pumax, 0, (size_t)Nn * NH * sizeof(unsigned), 0);
        cudaMemsetAsync(pden, 0, (size_t)Nn * NH * sizeof(float), 0);
        cudaMemsetAsync(phm, 0, (size_t)Nn * HID * sizeof(float), 0);

        edge_fused_kernel<<<gEb, 384, EDGE_SMEM>>>(pe, We_l, E, srcp, dstp,
                                                   pxl, pxr, attw + l * NH * 96,
                                                   plog, pumax);

        expsum_kernel<<<(E * NH + 255) / 256, 256>>>(dstp, plog, pumax, pden, E);
        agg_kernel<<<(E + 7) / 8, 256>>>(srcp, dstp, plog, pden, pxl, phm, E);
        nodeupd_kernel<<<(Nn + 7) / 8, 256>>>(cbias + l * HID, lng + l * HID,
                                              lnb + l * HID, (l < 2) ? 1 : 0, phm, px, Nn);
    }

    predictor_kernel<<<148, 256, PRED_SMEM>>>(
        srcp, dstp, px, pe,
        p1w, p1b, p1g, p1bt, p2w, p2b, p2g, p2bt, p3w, p3b, outp, E);
}

// round 9
// speedup vs baseline: 1.9386x; 1.0343x over previous
#include <cuda_runtime.h>
#include <math.h>

#define HID 96
#define HC  576
#define NH  6

typedef unsigned long long ull;

// ---------------- f32x2 packed helpers ----------------
__device__ __forceinline__ ull fma2(ull a, ull b, ull c) {
    ull d;
    asm("fma.rn.f32x2 %0, %1, %2, %3;" : "=l"(d) : "l"(a), "l"(b), "l"(c));
    return d;
}
__device__ __forceinline__ ull pack2(float x, float y) {
    ull r;
    asm("mov.b64 %0, {%1, %2};" : "=l"(r) : "f"(x), "f"(y));
    return r;
}
__device__ __forceinline__ ull dup2(float x) { return pack2(x, x); }
__device__ __forceinline__ float2 unpack2(ull v) {
    float2 r;
    asm("mov.b64 {%0, %1}, %2;" : "=f"(r.x), "=f"(r.y) : "l"(v));
    return r;
}
__device__ __forceinline__ unsigned f2tf32(float f) {
    unsigned r;
    asm("cvt.rna.tf32.f32 %0, %1;" : "=r"(r) : "f"(f));
    return r;
}
__device__ __forceinline__ ull pack_tf32(float a, float b) {
    unsigned lo = f2tf32(a), hi = f2tf32(b);
    ull r;
    asm("mov.b64 %0, {%1, %2};" : "=l"(r) : "r"(lo), "r"(hi));
    return r;
}
__device__ __forceinline__ void mma_tf32(float c[4],
    unsigned a0, unsigned a1, unsigned a2, unsigned a3,
    unsigned b0, unsigned b1)
{
    asm("mma.sync.aligned.m16n8k8.row.col.f32.tf32.tf32.f32 "
        "{%0,%1,%2,%3},{%4,%5,%6,%7},{%8,%9},{%0,%1,%2,%3};"
        : "+f"(c[0]), "+f"(c[1]), "+f"(c[2]), "+f"(c[3])
        : "r"(a0), "r"(a1), "r"(a2), "r"(a3), "r"(b0), "r"(b1));
}
__device__ __forceinline__ void red_add_v4(float* p, float4 v) {
    asm volatile("red.global.add.v4.f32 [%0], {%1, %2, %3, %4};"
                 :: "l"(p), "f"(v.x), "f"(v.y), "f"(v.z), "f"(v.w) : "memory");
}

// ---------------- scratch ----------------
__device__ float    g_x[20000 * HID];
__device__ float    g_eemb[200000 * HID];
__device__ float    g_eperm[200000 * HID];
__device__ float    g_xl[20000 * HC];
__device__ float    g_xr[20000 * HC];
__device__ float    g_logits[200000 * NH];
__device__ unsigned g_umax[20000 * NH];
__device__ float    g_den[20000 * NH];
__device__ float    g_hmean[20000 * HID];
__device__ int      g_cnt[20000];
__device__ int      g_cur[20000];
__device__ int      g_basep[20000];
__device__ int      g_perm[200000];
__device__ int      g_psrc[200000];
__device__ int      g_pdst[200000];

__device__ __forceinline__ float warpsum32(float v) {
#pragma unroll
    for (int m = 16; m; m >>= 1) v += __shfl_xor_sync(0xffffffffu, v, m);
    return v;
}

// ---------------- sort-by-dst kernels ----------------
__global__ void hist_kernel(const int* __restrict__ dst, int* __restrict__ cnt, int E) {
    int e = blockIdx.x * blockDim.x + threadIdx.x;
    if (e < E) atomicAdd(&cnt[dst[e]], 1);
}
__global__ void scan_kernel(const int* __restrict__ cnt, int* __restrict__ base, int Nn) {
    __shared__ int part[1024];
    int t = threadIdx.x;
    int start = t * 20;
    int s = 0;
#pragma unroll
    for (int i = 0; i < 20; i++) { int idx = start + i; if (idx < Nn) s += cnt[idx]; }
    part[t] = s;
    __syncthreads();
    for (int off = 1; off < 1024; off <<= 1) {
        int v = (t >= off) ? part[t - off] : 0;
        __syncthreads();
        part[t] += v;
        __syncthreads();
    }
    int run = (t > 0) ? part[t - 1] : 0;
#pragma unroll
    for (int i = 0; i < 20; i++) {
        int idx = start + i;
        if (idx < Nn) { base[idx] = run; run += cnt[idx]; }
    }
}
__global__ void scatter_kernel(const int* __restrict__ src, const int* __restrict__ dst,
                               const int* __restrict__ base, int* __restrict__ cur,
                               int* __restrict__ perm, int* __restrict__ psrc,
                               int* __restrict__ pdst, int E)
{
    int e = blockIdx.x * blockDim.x + threadIdx.x;
    if (e >= E) return;
    int d = dst[e];
    int pos = base[d] + atomicAdd(&cur[d], 1);
    perm[pos] = e;
    psrc[pos] = src[e];
    pdst[pos] = d;
}
__global__ void permute_rows_kernel(const float* __restrict__ in, const int* __restrict__ perm,
                                    float* __restrict__ out, int E)
{
    int e = blockIdx.x * 8 + (threadIdx.x >> 5);
    int lane = threadIdx.x & 31;
    if (e >= E) return;
    int se = perm[e];
    if (lane < 24)
        ((float4*)(out + (size_t)e * HID))[lane] =
            ((const float4*)(in + (size_t)se * HID))[lane];
}

// ---------------- encoder ----------------
__global__ void encoder_kernel(const float* __restrict__ in, int Fin,
                               const float* __restrict__ W, const float* __restrict__ b,
                               const float* __restrict__ g, const float* __restrict__ beta,
                               float* __restrict__ out, int M)
{
    int w    = (blockIdx.x * blockDim.x + threadIdx.x) >> 5;
    int lane = threadIdx.x & 31;
    if (w >= M) return;
    float xin[4];
#pragma unroll
    for (int k = 0; k < 4; k++) xin[k] = (k < Fin) ? in[(size_t)w * Fin + k] : 0.f;
    float v[3];
#pragma unroll
    for (int j = 0; j < 3; j++) {
        int c = lane + 32 * j;
        float acc = b[c];
        for (int k = 0; k < Fin; k++) acc = fmaf(xin[k], W[k * HID + c], acc);
        v[j] = acc;
    }
    float mu = warpsum32(v[0] + v[1] + v[2]) * (1.f / 96.f);
    float q = 0.f;
#pragma unroll
    for (int j = 0; j < 3; j++) { float d = v[j] - mu; q = fmaf(d, d, q); }
    float rstd = rsqrtf(warpsum32(q) * (1.f / 96.f) + 1e-5f);
#pragma unroll
    for (int j = 0; j < 3; j++) {
        int c = lane + 32 * j;
        float y = (v[j] - mu) * rstd * g[c] + beta[c];
        out[(size_t)w * HID + c] = fmaxf(y, 0.f);
    }
}

// ---------------- dual node tf32 GEMM: xl & xr from one A staging ----------
#define AU_ULL (12 * 512)
#define BU_ULL (12 * 384)
#define TFD_SMEM ((AU_ULL + 2 * BU_ULL) * 8)

__global__ __launch_bounds__(384) void tf32_dual_gemm_kernel(
    const float* __restrict__ Ag,
    const float* __restrict__ Bl, const float* __restrict__ Br,
    const float* __restrict__ bl, const float* __restrict__ br,
    float* __restrict__ Cl, float* __restrict__ Cr, int M)
{
    extern __shared__ ull sh64[];
    ull* Au  = sh64;
    ull* BuL = sh64 + AU_ULL;
    ull* BuR = BuL + BU_ULL;

    int tid = threadIdx.x;
    int m0 = blockIdx.x * 128, n0 = blockIdx.y * 96;

    {
        int row = tid & 127;
        int kg  = tid >> 7;
        int m = m0 + row;
        const float* arow = Ag + (size_t)m * 96;
#pragma unroll
        for (int i = 0; i < 4; i++) {
            int ks = kg * 4 + i;
            float4 lo = make_float4(0.f, 0.f, 0.f, 0.f);
            float4 hi = make_float4(0.f, 0.f, 0.f, 0.f);
            if (m < M) {
                lo = *(const float4*)(arow + ks * 8);
                hi = *(const float4*)(arow + ks * 8 + 4);
            }
            ull* dstp = Au + ks * 512 + row * 4;
            *(ulonglong2*)(dstp)     = make_ulonglong2(pack_tf32(lo.x, hi.x), pack_tf32(lo.y, hi.y));
            *(ulonglong2*)(dstp + 2) = make_ulonglong2(pack_tf32(lo.z, hi.z), pack_tf32(lo.w, hi.w));
        }
    }
    for (int t = tid; t < 2304; t += 384) {
        int side = t >= 1152;
        int tt = t - side * 1152;
        int ks  = tt / 96;
        int rem = tt - ks * 96;
        int q = rem >> 2, r = rem & 3;
        const float* Bg = side ? Br : Bl;
        const float* b0 = Bg + (size_t)(ks * 8 + r) * HC + n0 + q * 4;
        float4 lo = *(const float4*)b0;
        float4 hi = *(const float4*)(b0 + 4 * HC);
        ull* dstb = (side ? BuR : BuL) + ks * 384 + q * 16 + r;
        dstb[0]  = pack_tf32(lo.x, hi.x);
        dstb[4]  = pack_tf32(lo.y, hi.y);
        dstb[8]  = pack_tf32(lo.z, hi.z);
        dstb[12] = pack_tf32(lo.w, hi.w);
    }
    __syncthreads();

    int wid = tid >> 5, lane = tid & 31;
    int wm = wid & 3, wn = wid >> 2;
    int g = lane >> 2, tig = lane & 3;
    int rowb = wm * 32, colb = wn * 32;

#pragma unroll
    for (int side = 0; side < 2; side++) {
        const ull* Bu = side ? BuR : BuL;
        const float* bias = side ? br : bl;
        float* C = side ? Cr : Cl;

        float acc[2][4][4];
#pragma unroll
        for (int mt = 0; mt < 2; mt++)
#pragma unroll
            for (int nt = 0; nt < 4; nt++)
#pragma unroll
                for (int q = 0; q < 4; q++) acc[mt][nt][q] = 0.f;

#pragma unroll
        for (int ks = 0; ks < 12; ks++) {
            const ull* Ak = Au + ks * 512;
            const ull* Bk = Bu + ks * 384;
            uint2 pa[2][2];
#pragma unroll
            for (int mt = 0; mt < 2; mt++) {
                int rb = rowb + mt * 16 + g;
                pa[mt][0] = *(const uint2*)(Ak + rb * 4 + tig);
                pa[mt][1] = *(const uint2*)(Ak + (rb + 8) * 4 + tig);
            }
#pragma unroll
            for (int nt = 0; nt < 4; nt++) {
                int cb = colb + nt * 8 + g;
                uint2 pb = *(const uint2*)(Bk + cb * 4 + tig);
#pragma unroll
                for (int mt = 0; mt < 2; mt++)
                    mma_tf32(acc[mt][nt],
                             pa[mt][0].x, pa[mt][1].x, pa[mt][0].y, pa[mt][1].y,
                             pb.x, pb.y);
            }
        }

#pragma unroll
        for (int nt = 0; nt < 4; nt++) {
            int c = n0 + colb + nt * 8 + 2 * tig;
            float2 bq = *(const float2*)(bias + c);
#pragma unroll
            for (int mt = 0; mt < 2; mt++) {
                int r0 = m0 + rowb + mt * 16 + g;
                if (r0 < M) {
                    float2 o = make_float2(acc[mt][nt][0] + bq.x, acc[mt][nt][1] + bq.y);
                    *(float2*)(C + (size_t)r0 * HC + c) = o;
                }
                int r1 = r0 + 8;
                if (r1 < M) {
                    float2 o = make_float2(acc[mt][nt][2] + bq.x, acc[mt][nt][3] + bq.y);
                    *(float2*)(C + (size_t)r1 * HC + c) = o;
                }
            }
        }
    }
}

// ---------------- fused edge kernel: all 6 heads per block (dst-sorted) -----
#define EAU (12 * 512)
#define EBU (12 * 384)
#define EDGE_SMEM ((EAU + 2 * EBU) * 8 + 128 * 8 * 4 + 128 * 2 * 4)

__global__ __launch_bounds__(384) void edge_fused_kernel(
    const float* __restrict__ Ag, const float* __restrict__ Bg, int M,
    const int* __restrict__ src, const int* __restrict__ dst,
    const float* __restrict__ xl, const float* __restrict__ xr,
    const float* __restrict__ attw, float* __restrict__ logits,
    unsigned* __restrict__ umax)
{
    extern __shared__ ull sh64[];
    ull* Au  = sh64;
    ull* Bu0 = sh64 + EAU;
    ull* Bu1 = Bu0 + EBU;
    float* s_logit = (float*)(Bu1 + EBU);
    int*   s_src   = (int*)(s_logit + 128 * 8);
    int*   s_dst   = s_src + 128;

    int tid = threadIdx.x;
    int m0 = blockIdx.x * 128;

    for (int i = tid; i < 128 * 8; i += 384) s_logit[i] = 0.f;
    if (tid < 128) {
        int e = m0 + tid;
        int ec = (e < M) ? e : (M - 1);
        s_src[tid] = src[ec];
        s_dst[tid] = dst[ec];
    }

    {
        int row = tid & 127;
        int kg  = tid >> 7;
        int m = m0 + row;
        const float* arow = Ag + (size_t)m * 96;
#pragma unroll
        for (int i = 0; i < 4; i++) {
            int ks = kg * 4 + i;
            float4 lo = make_float4(0.f, 0.f, 0.f, 0.f);
            float4 hi = make_float4(0.f, 0.f, 0.f, 0.f);
            if (m < M) {
                lo = *(const float4*)(arow + ks * 8);
                hi = *(const float4*)(arow + ks * 8 + 4);
            }
            ull* dstp = Au + ks * 512 + row * 4;
            *(ulonglong2*)(dstp)     = make_ulonglong2(pack_tf32(lo.x, hi.x), pack_tf32(lo.y, hi.y));
            *(ulonglong2*)(dstp + 2) = make_ulonglong2(pack_tf32(lo.z, hi.z), pack_tf32(lo.w, hi.w));
        }
    }
    for (int t = tid; t < 1152; t += 384) {
        int ks  = t / 96;
        int rem = t - ks * 96;
        int q = rem >> 2, r = rem & 3;
        const float* b0 = Bg + (size_t)(ks * 8 + r) * HC + q * 4;
        float4 lo = *(const float4*)b0;
        float4 hi = *(const float4*)(b0 + 4 * HC);
        ull* dstb = Bu0 + ks * 384 + q * 16 + r;
        dstb[0]  = pack_tf32(lo.x, hi.x);
        dstb[4]  = pack_tf32(lo.y, hi.y);
        dstb[8]  = pack_tf32(lo.z, hi.z);
        dstb[12] = pack_tf32(lo.w, hi.w);
    }
    __syncthreads();

    int wid = tid >> 5, lane = tid & 31;
    int wm = wid & 3, wn = wid >> 2;
    int g = lane >> 2, tig = lane & 3;
    int rowb = wm * 32, colb = wn * 32;

    for (int h = 0; h < NH; h++) {
        ull* Bcur = (h & 1) ? Bu1 : Bu0;
        float4 plo[3], phi[3];
        if (h < 5) {
#pragma unroll
            for (int it = 0; it < 3; it++) {
                int t = tid + 384 * it;
                int ks  = t / 96;
                int rem = t - ks * 96;
                int q = rem >> 2, r = rem & 3;
                const float* b0 = Bg + (size_t)(ks * 8 + r) * HC + (h + 1) * 96 + q * 4;
                plo[it] = *(const float4*)b0;
                phi[it] = *(const float4*)(b0 + 4 * HC);
            }
        }

        float acc[2][4][4];
#pragma unroll
        for (int mt = 0; mt < 2; mt++)
#pragma unroll
            for (int nt = 0; nt < 4; nt++)
#pragma unroll
                for (int q = 0; q < 4; q++) acc[mt][nt][q] = 0.f;

#pragma unroll
        for (int ks = 0; ks < 12; ks++) {
            const ull* Ak = Au + ks * 512;
            const ull* Bk = Bcur + ks * 384;
            uint2 pa[2][2];
#pragma unroll
            for (int mt = 0; mt < 2; mt++) {
                int rb = rowb + mt * 16 + g;
                pa[mt][0] = *(const uint2*)(Ak + rb * 4 + tig);
                pa[mt][1] = *(const uint2*)(Ak + (rb + 8) * 4 + tig);
            }
#pragma unroll
            for (int nt = 0; nt < 4; nt++) {
                int cb = colb + nt * 8 + g;
                uint2 pb = *(const uint2*)(Bk + cb * 4 + tig);
#pragma unroll
                for (int mt = 0; mt < 2; mt++)
                    mma_tf32(acc[mt][nt],
                             pa[mt][0].x, pa[mt][1].x, pa[mt][0].y, pa[mt][1].y,
                             pb.x, pb.y);
            }
        }

#pragma unroll
        for (int mt = 0; mt < 2; mt++) {
#pragma unroll
            for (int half = 0; half < 2; half++) {
                int ml = rowb + mt * 16 + half * 8 + g;
                int m = m0 + ml;
                float partial = 0.f;
                if (m < M) {
                    int s = s_src[ml], d = s_dst[ml];
                    const float* xls = xl + (size_t)s * HC;
                    const float* xrd = xr + (size_t)d * HC;
#pragma unroll
                    for (int nt = 0; nt < 4; nt++) {
                        int c = h * 96 + colb + nt * 8 + 2 * tig;
                        float2 xlv = *(const float2*)(xls + c);
                        float2 xrv = *(const float2*)(xrd + c);
                        float aw0 = attw[c], aw1 = attw[c + 1];
                        float a0 = acc[mt][nt][half * 2 + 0];
                        float a1 = acc[mt][nt][half * 2 + 1];
                        float t0 = a0 + xlv.x + xrv.x; t0 = (t0 > 0.f) ? t0 : 0.2f * t0;
                        float t1 = a1 + xlv.y + xrv.y; t1 = (t1 > 0.f) ? t1 : 0.2f * t1;
                        partial = fmaf(t0, aw0, fmaf(t1, aw1, partial));
                    }
                }
                partial += __shfl_down_sync(0xffffffffu, partial, 1, 4);
                partial += __shfl_down_sync(0xffffffffu, partial, 2, 4);
                if (tig == 0 && m < M)
                    atomicAdd(&s_logit[ml * 8 + h], partial);
            }
        }

        if (h < 5) {
            ull* Bnext = (h & 1) ? Bu0 : Bu1;
#pragma unroll
            for (int it = 0; it < 3; it++) {
                int t = tid + 384 * it;
                int ks  = t / 96;
                int rem = t - ks * 96;
                int q = rem >> 2, r = rem & 3;
                ull* dstb = Bnext + ks * 384 + q * 16 + r;
                dstb[0]  = pack_tf32(plo[it].x, phi[it].x);
                dstb[4]  = pack_tf32(plo[it].y, phi[it].y);
                dstb[8]  = pack_tf32(plo[it].z, phi[it].z);
                dstb[12] = pack_tf32(plo[it].w, phi[it].w);
            }
        }
        __syncthreads();
    }

    for (int t = tid; t < 128 * NH; t += 384) {
        int el = t / NH, h = t - el * NH;
        int e = m0 + el;
        if (e < M) {
            float lg = s_logit[el * 8 + h];
            logits[(size_t)e * NH + h] = lg;
            unsigned u = __float_as_uint(lg);
            u ^= (u >> 31) ? 0xFFFFFFFFu : 0x80000000u;
            atomicMax(&umax[s_dst[el] * NH + h], u);
        }
    }
}

// ---------------- exp + denominator ----------------
__global__ void expsum_kernel(const int* __restrict__ dst, float* __restrict__ logits,
                              const unsigned* __restrict__ umax, float* __restrict__ den, int E)
{
    int t = blockIdx.x * blockDim.x + threadIdx.x;
    if (t >= E * NH) return;
    int e = t / NH, h = t - e * NH;
    int d = dst[e];
    unsigned u = umax[d * NH + h];
    float m = (u & 0x80000000u) ? __uint_as_float(u ^ 0x80000000u) : __uint_as_float(~u);
    float ex = expf(logits[t] - m);
    logits[t] = ex;
    atomicAdd(&den[d * NH + h], ex);
}

// ---------------- aggregate (red.v4) ----------------
__global__ void agg_kernel(const int* __restrict__ src, const int* __restrict__ dst,
                           const float* __restrict__ ex, const float* __restrict__ den,
                           const float* __restrict__ xl, float* __restrict__ hmean, int E)
{
    int e    = (blockIdx.x * blockDim.x + threadIdx.x) >> 5;
    int lane = threadIdx.x & 31;
    if (e >= E) return;
    int s = src[e], d = dst[e];
    float a = 0.f;
    if (lane < NH) a = ex[e * NH + lane] / (den[d * NH + lane] + 1e-16f);
    float alpha[NH];
#pragma unroll
    for (int h = 0; h < NH; h++) alpha[h] = __shfl_sync(0xffffffffu, a, h) * (1.f / 6.f);
    if (lane < 24) {
        const float* xls = xl + (size_t)s * HC + lane * 4;
        float4 v = make_float4(0.f, 0.f, 0.f, 0.f);
#pragma unroll
        for (int h = 0; h < NH; h++) {
            float4 xv = *(const float4*)(xls + h * 96);
            v.x = fmaf(alpha[h], xv.x, v.x);
            v.y = fmaf(alpha[h], xv.y, v.y);
            v.z = fmaf(alpha[h], xv.z, v.z);
            v.w = fmaf(alpha[h], xv.w, v.w);
        }
        red_add_v4(hmean + (size_t)d * HID + lane * 4, v);
    }
}

// ---------------- node update ----------------
__global__ void nodeupd_kernel(const float* __restrict__ cb, const float* __restrict__ g,
                               const float* __restrict__ bt, int doElu,
                               const float* __restrict__ hmean, float* __restrict__ x, int M)
{
    int n    = (blockIdx.x * blockDim.x + threadIdx.x) >> 5;
    int lane = threadIdx.x & 31;
    if (n >= M) return;
    float v[3];
#pragma unroll
    for (int j = 0; j < 3; j++) {
        int c = lane + 32 * j;
        float hv = hmean[(size_t)n * HID + c] + cb[c];
        if (doElu) hv = (hv > 0.f) ? hv : (expf(hv) - 1.f);
        v[j] = hv;
    }
    float mu = warpsum32(v[0] + v[1] + v[2]) * (1.f / 96.f);
    float q = 0.f;
#pragma unroll
    for (int j = 0; j < 3; j++) { float d = v[j] - mu; q = fmaf(d, d, q); }
    float rstd = rsqrtf(warpsum32(q) * (1.f / 96.f) + 1e-5f);
#pragma unroll
    for (int j = 0; j < 3; j++) {
        int c = lane + 32 * j;
        float y = (v[j] - mu) * rstd * g[c] + bt[c];
        x[(size_t)n * HID + c] += y;
    }
}

// ---------------- persistent fused predictor MLP ----------------
#define PF_P1W 36864
#define PF_P3W 64
#define PF_C1  384
#define PF_C2  192
#define PF_CTX_U64 (32 * 288)
#define PRED_SMEM ((PF_P1W + PF_P3W + PF_C1 + PF_C2) * 4 + PF_CTX_U64 * 8)

__global__ __launch_bounds__(256) void predictor_kernel(
    const int* __restrict__ src, const int* __restrict__ dst,
    const float* __restrict__ xnode, const float* __restrict__ eemb,
    const float* __restrict__ p1w, const float* __restrict__ p1b,
    const float* __restrict__ p1g, const float* __restrict__ p1bt,
    const float* __restrict__ p2w, const float* __restrict__ p2b,
    const float* __restrict__ p2g, const float* __restrict__ p2bt,
    const float* __restrict__ p3w, const float* __restrict__ p3b,
    float* __restrict__ out, int E)
{
    extern __shared__ float sm[];
    float* s_p1w = sm;
    float* s_p3w = s_p1w + PF_P1W;
    float* s_c1  = s_p3w + PF_P3W;
    float* s_c2  = s_c1 + PF_C1;
    ull*   s_ctx = (ull*)(s_c2 + PF_C2);

    int tid = threadIdx.x;
    for (int i = tid; i < PF_P1W / 4; i += 256) ((float4*)s_p1w)[i] = ((const float4*)p1w)[i];
    if (tid < 64) s_p3w[tid] = p3w[tid];
    if (tid < 128) { s_c1[tid] = p1b[tid]; s_c1[128 + tid] = p1g[tid]; s_c1[256 + tid] = p1bt[tid]; }
    if (tid < 64)  { s_c2[tid] = p2b[tid]; s_c2[64 + tid] = p2g[tid]; s_c2[128 + tid] = p2bt[tid]; }
    float pb = p3b[0];

    int w = tid >> 5, lane = tid & 31;
    int j1 = lane * 4;
    int j2 = lane * 2;
    int NB = (E + 63) / 64;

    for (int bb = blockIdx.x; bb < NB; bb += gridDim.x) {
        __syncthreads();
        for (int i = tid; i < 64 * 72; i += 256) {
            int el = i / 72, kq = (i - el * 72) * 4;
            int e = bb * 64 + el; if (e > E - 1) e = E - 1;
            float4 v;
            if (kq < 96)       v = *(const float4*)(xnode + (size_t)src[e] * HID + kq);
            else if (kq < 192) v = *(const float4*)(xnode + (size_t)dst[e] * HID + (kq - 96));
            else               v = *(const float4*)(eemb + (size_t)e * HID + (kq - 192));
            float* base = (float*)(s_ctx + (size_t)(el >> 1) * 288 + kq);
            int hoff = el & 1;
            base[0 + hoff] = v.x; base[2 + hoff] = v.y;
            base[4 + hoff] = v.z; base[6 + hoff] = v.w;
        }
        __syncthreads();

        const ull* cp0 = s_ctx + (size_t)(4 * w + 0) * 288;
        const ull* cp1 = s_ctx + (size_t)(4 * w + 1) * 288;
        const ull* cp2 = s_ctx + (size_t)(4 * w + 2) * 288;
        const ull* cp3 = s_ctx + (size_t)(4 * w + 3) * 288;

        ull acc1[4][4];
#pragma unroll
        for (int q = 0; q < 4; q++)
#pragma unroll
            for (int j = 0; j < 4; j++) acc1[q][j] = 0ull;

#pragma unroll 4
        for (int k = 0; k < 288; k++) {
            ull c0 = cp0[k], c1 = cp1[k], c2 = cp2[k], c3 = cp3[k];
            float4 wv = *(const float4*)(s_p1w + k * 128 + j1);
            ull w0 = dup2(wv.x), w1 = dup2(wv.y), w2 = dup2(wv.z), w3 = dup2(wv.w);
            acc1[0][0] = fma2(c0, w0, acc1[0][0]); acc1[0][1] = fma2(c0, w1, acc1[0][1]);
            acc1[0][2] = fma2(c0, w2, acc1[0][2]); acc1[0][3] = fma2(c0, w3, acc1[0][3]);
            acc1[1][0] = fma2(c1, w0, acc1[1][0]); acc1[1][1] = fma2(c1, w1, acc1[1][1]);
            acc1[1][2] = fma2(c1, w2, acc1[1][2]); acc1[1][3] = fma2(c1, w3, acc1[1][3]);
            acc1[2][0] = fma2(c2, w0, acc1[2][0]); acc1[2][1] = fma2(c2, w1, acc1[2][1]);
            acc1[2][2] = fma2(c2, w2, acc1[2][2]); acc1[2][3] = fma2(c2, w3, acc1[2][3]);
            acc1[3][0] = fma2(c3, w0, acc1[3][0]); acc1[3][1] = fma2(c3, w1, acc1[3][1]);
            acc1[3][2] = fma2(c3, w2, acc1[3][2]); acc1[3][3] = fma2(c3, w3, acc1[3][3]);
        }

        float hE[4][4], hO[4][4];
#pragma unroll
        for (int q = 0; q < 4; q++)
#pragma unroll
            for (int j = 0; j < 4; j++) {
                float2 u = unpack2(acc1[q][j]);
                hE[q][j] = u.x + s_c1[j1 + j];
                hO[q][j] = u.y + s_c1[j1 + j];
            }
#pragma unroll
        for (int q = 0; q < 4; q++) {
            float sE = hE[q][0] + hE[q][1] + hE[q][2] + hE[q][3];
            float sO = hO[q][0] + hO[q][1] + hO[q][2] + hO[q][3];
            float muE = warpsum32(sE) * (1.f / 128.f);
            float muO = warpsum32(sO) * (1.f / 128.f);
            float qE = 0.f, qO = 0.f;
#pragma unroll
            for (int j = 0; j < 4; j++) {
                float d;
                d = hE[q][j] - muE; qE = fmaf(d, d, qE);
                d = hO[q][j] - muO; qO = fmaf(d, d, qO);
            }
            float rE = rsqrtf(warpsum32(qE) * (1.f / 128.f) + 1e-5f);
            float rO = rsqrtf(warpsum32(qO) * (1.f / 128.f) + 1e-5f);
#pragma unroll
            for (int j = 0; j < 4; j++) {
                float gma = s_c1[128 + j1 + j], bta = s_c1[256 + j1 + j];
                hE[q][j] = fmaxf((hE[q][j] - muE) * rE * gma + bta, 0.f);
                hO[q][j] = fmaxf((hO[q][j] - muO) * rO * gma + bta, 0.f);
            }
        }
        __syncwarp();
#pragma unroll
        for (int q = 0; q < 4; q++) {
            ull* hp = s_ctx + (size_t)(4 * w + q) * 288;
#pragma unroll
            for (int j = 0; j < 4; j++)
                hp[j1 + j] = pack2(hE[q][j], hO[q][j]);
        }
        __syncwarp();

        ull acc2[4][2];
#pragma unroll
        for (int q = 0; q < 4; q++) { acc2[q][0] = 0ull; acc2[q][1] = 0ull; }
#pragma unroll 4
        for (int k = 0; k < 128; k++) {
            ull c0 = cp0[k], c1 = cp1[k], c2 = cp2[k], c3 = cp3[k];
            float2 wv = __ldg((const float2*)(p2w + k * 64 + j2));
            ull w0 = dup2(wv.x), w1 = dup2(wv.y);
            acc2[0][0] = fma2(c0, w0, acc2[0][0]); acc2[0][1] = fma2(c0, w1, acc2[0][1]);
            acc2[1][0] = fma2(c1, w0, acc2[1][0]); acc2[1][1] = fma2(c1, w1, acc2[1][1]);
            acc2[2][0] = fma2(c2, w0, acc2[2][0]); acc2[2][1] = fma2(c2, w1, acc2[2][1]);
            acc2[3][0] = fma2(c3, w0, acc2[3][0]); acc2[3][1] = fma2(c3, w1, acc2[3][1]);
        }

        float gEo[4][2], gOo[4][2];
#pragma unroll
        for (int q = 0; q < 4; q++)
#pragma unroll
            for (int j = 0; j < 2; j++) {
                float2 u = unpack2(acc2[q][j]);
                gEo[q][j] = u.x + s_c2[j2 + j];
                gOo[q][j] = u.y + s_c2[j2 + j];
            }
#pragma unroll
        for (int q = 0; q < 4; q++) {
            float sE = gEo[q][0] + gEo[q][1];
            float sO = gOo[q][0] + gOo[q][1];
            float muE = warpsum32(sE) * (1.f / 64.f);
            float muO = warpsum32(sO) * (1.f / 64.f);
            float qE = 0.f, qO = 0.f;
#pragma unroll
            for (int j = 0; j < 2; j++) {
                float d;
                d = gEo[q][j] - muE; qE = fmaf(d, d, qE);
                d = gOo[q][j] - muO; qO = fmaf(d, d, qO);
            }
            float rE = rsqrtf(warpsum32(qE) * (1.f / 64.f) + 1e-5f);
            float rO = rsqrtf(warpsum32(qO) * (1.f / 64.f) + 1e-5f);
            float oE = 0.f, oO = 0.f;
#pragma unroll
            for (int j = 0; j < 2; j++) {
                float gma = s_c2[64 + j2 + j], bta = s_c2[128 + j2 + j];
                float vE = fmaxf((gEo[q][j] - muE) * rE * gma + bta, 0.f);
                float vO = fmaxf((gOo[q][j] - muO) * rO * gma + bta, 0.f);
                float w3v = s_p3w[j2 + j];
                oE = fmaf(vE, w3v, oE);
                oO = fmaf(vO, w3v, oO);
            }
            oE = warpsum32(oE);
            oO = warpsum32(oO);
            if (lane == 0) {
                int e0 = bb * 64 + 8 * w + 2 * q;
                if (e0 < E) out[e0] = oE + pb;
                if (e0 + 1 < E) out[e0 + 1] = oO + pb;
            }
        }
    }
}

// ---------------- launch ----------------
extern "C" void kernel_launch(void* const* d_in, const int* in_sizes, int n_in,
                              void* d_out, int out_size)
{
    const float* x         = (const float*)d_in[0];
    const float* edge_attr = (const float*)d_in[1];
    const int*   edge_idx  = (const int*)d_in[2];
    const float* ne_w = (const float*)d_in[3];
    const float* ne_b = (const float*)d_in[4];
    const float* ne_g = (const float*)d_in[5];
    const float* ne_bt = (const float*)d_in[6];
    const float* ee_w = (const float*)d_in[7];
    const float* ee_b = (const float*)d_in[8];
    const float* ee_g = (const float*)d_in[9];
    const float* ee_bt = (const float*)d_in[10];
    const float* Wl = (const float*)d_in[11];
    const float* bl = (const float*)d_in[12];
    const float* Wr = (const float*)d_in[13];
    const float* br = (const float*)d_in[14];
    const float* We = (const float*)d_in[15];
    const float* attw = (const float*)d_in[16];
    const float* cbias = (const float*)d_in[17];
    const float* lng = (const float*)d_in[18];
    const float* lnb = (const float*)d_in[19];
    const float* p1w = (const float*)d_in[20];
    const float* p1b = (const float*)d_in[21];
    const float* p1g = (const float*)d_in[22];
    const float* p1bt = (const float*)d_in[23];
    const float* p2w = (const float*)d_in[24];
    const float* p2b = (const float*)d_in[25];
    const float* p2g = (const float*)d_in[26];
    const float* p2bt = (const float*)d_in[27];
    const float* p3w = (const float*)d_in[28];
    const float* p3b = (const float*)d_in[29];

    int Nn = in_sizes[0] / 4;
    int E  = in_sizes[1] / 3;
    const int* srcp = edge_idx;
    const int* dstp = edge_idx + E;
    float* outp = (float*)d_out;

    void *px_, *pe_, *pep_, *pxl_, *pxr_, *plog_, *pumax_, *pden_, *phm_;
    void *pcnt_, *pcur_, *pbase_, *pperm_, *ppsrc_, *ppdst_;
    cudaGetSymbolAddress(&px_, g_x);
    cudaGetSymbolAddress(&pe_, g_eemb);
    cudaGetSymbolAddress(&pep_, g_eperm);
    cudaGetSymbolAddress(&pxl_, g_xl);
    cudaGetSymbolAddress(&pxr_, g_xr);
    cudaGetSymbolAddress(&plog_, g_logits);
    cudaGetSymbolAddress(&pumax_, g_umax);
    cudaGetSymbolAddress(&pden_, g_den);
    cudaGetSymbolAddress(&phm_, g_hmean);
    cudaGetSymbolAddress(&pcnt_, g_cnt);
    cudaGetSymbolAddress(&pcur_, g_cur);
    cudaGetSymbolAddress(&pbase_, g_basep);
    cudaGetSymbolAddress(&pperm_, g_perm);
    cudaGetSymbolAddress(&ppsrc_, g_psrc);
    cudaGetSymbolAddress(&ppdst_, g_pdst);
    float* px = (float*)px_;   float* pe = (float*)pe_;   float* pep = (float*)pep_;
    float* pxl = (float*)pxl_; float* pxr = (float*)pxr_;
    float* plog = (float*)plog_;
    unsigned* pumax = (unsigned*)pumax_;
    float* pden = (float*)pden_; float* phm = (float*)phm_;
    int* pcnt = (int*)pcnt_; int* pcur = (int*)pcur_; int* pbase = (int*)pbase_;
    int* pperm = (int*)pperm_; int* ppsrc = (int*)ppsrc_; int* ppdst = (int*)ppdst_;

    cudaFuncSetAttribute(tf32_dual_gemm_kernel,
                         cudaFuncAttributeMaxDynamicSharedMemorySize, TFD_SMEM);
    cudaFuncSetAttribute(edge_fused_kernel,
                         cudaFuncAttributeMaxDynamicSharedMemorySize, EDGE_SMEM);
    cudaFuncSetAttribute(predictor_kernel,
                         cudaFuncAttributeMaxDynamicSharedMemorySize, PRED_SMEM);

    // encoders
    encoder_kernel<<<(Nn + 7) / 8, 256>>>(x, 4, ne_w, ne_b, ne_g, ne_bt, px, Nn);
    encoder_kernel<<<(E + 7) / 8, 256>>>(edge_attr, 3, ee_w, ee_b, ee_g, ee_bt, pe, E);

    // sort edges by dst (counting sort) + permuted eemb
    cudaMemsetAsync(pcnt, 0, (size_t)Nn * sizeof(int), 0);
    cudaMemsetAsync(pcur, 0, (size_t)Nn * sizeof(int), 0);
    hist_kernel<<<(E + 255) / 256, 256>>>(dstp, pcnt, E);
    scan_kernel<<<1, 1024>>>(pcnt, pbase, Nn);
    scatter_kernel<<<(E + 255) / 256, 256>>>(srcp, dstp, pbase, pcur,
                                             pperm, ppsrc, ppdst, E);
    permute_rows_kernel<<<(E + 7) / 8, 256>>>(pe, pperm, pep, E);

    dim3 gNt((Nn + 127) / 128, HC / 96);
    int gEb = (E + 127) / 128;

    for (int l = 0; l < 3; l++) {
        const float* Wl_l = Wl + (size_t)l * 96 * HC;
        const float* Wr_l = Wr + (size_t)l * 96 * HC;
        const float* We_l = We + (size_t)l * 96 * HC;
        tf32_dual_gemm_kernel<<<gNt, 384, TFD_SMEM>>>(px, Wl_l, Wr_l,
                                                      bl + l * HC, br + l * HC,
                                                      pxl, pxr, Nn);

        cudaMemsetAsync(pumax, 0, (size_t)Nn * NH * sizeof(unsigned), 0);
        cudaMemsetAsync(pden, 0, (size_t)Nn * NH * sizeof(float), 0);
        cudaMemsetAsync(phm, 0, (size_t)Nn * HID * sizeof(float), 0);

        edge_fused_kernel<<<gEb, 384, EDGE_SMEM>>>(pep, We_l, E, ppsrc, ppdst,
                                                   pxl, pxr, attw + l * NH * 96,
                                                   plog, pumax);

        expsum_kernel<<<(E * NH + 255) / 256, 256>>>(ppdst, plog, pumax, pden, E);
        agg_kernel<<<(E + 7) / 8, 256>>>(ppsrc, ppdst, plog, pden, pxl, phm, E);
        nodeupd_kernel<<<(Nn + 7) / 8, 256>>>(cbias + l * HID, lng + l * HID,
                                              lnb + l * HID, (l < 2) ? 1 : 0, phm, px, Nn);
    }

    predictor_kernel<<<148, 256, PRED_SMEM>>>(
        srcp, dstp, px, pe,
        p1w, p1b, p1g, p1bt, p2w, p2b, p2g, p2bt, p3w, p3b, outp, E);
}